// round 14
// baseline (speedup 1.0000x reference)
#include <cuda_runtime.h>
#include <cuda_fp16.h>
#include <math.h>
#include <stdint.h>

typedef unsigned long long ull;

constexpr int Bn=2, Vn=8, Cn=64, An=256;
constexpr int HWn=128*128, Pn=An*An;
constexpr int C3n=194, COn=192, HIDn=48;

constexpr size_t CTXN=(size_t)Bn*C3n*Pn;
constexpr size_t CNTN=(size_t)Bn*3*Pn;
constexpr size_t OFF_COV =(size_t)3*Bn*Cn*Pn;
constexpr size_t OFF_UNC =OFF_COV+(size_t)Bn*Pn;
constexpr size_t OFF_CONF=OFF_UNC+(size_t)Bn*Pn;

constexpr int NG1=21;    // 3 dy * 7 cib   (K=96 per group: 3dx x 32ci)
constexpr int NG2=18;    // 3 dy * 6 cib
constexpr int BROW=104;  // B row pitch in halfwords (96 valid k + pad)

__device__ float  g_ctx[CTXN];
__device__ float  g_cnt[CNTN];
__device__ float  g_uraw[(size_t)Bn*Pn];
__device__ int    g_umax[Bn];
__device__ int    g_idx[Bn*Vn*HWn];
__device__ float  g_wts[3][Bn*Vn*HWn];
__device__ float  g_h1[(size_t)Bn*COn*Pn];
__device__ float  g_h2[(size_t)Bn*COn*Pn];
__device__ uint32_t g_ctxh[(size_t)Bn*112*Pn];   // fp16 pair-packed ctx (97 valid ci2)
__device__ uint32_t g_h1h [(size_t)Bn*96*Pn];    // fp16 pair-packed silu(GN1(h1))
__device__ unsigned short g_wTc1h[NG1*192*BROW]; // fp16 [grp][co][104k]
__device__ unsigned short g_wTc2h[NG2*192*BROW];
__device__ float  g_csum[Bn*COn*2];
__device__ float  g_sA[Bn*COn], g_sB[Bn*COn];
__device__ float  g_gate[Bn*COn];
__device__ float  g_pool[Bn*COn];

__device__ __forceinline__ float siluf(float x){ return x/(1.f+__expf(-x)); }
__device__ __forceinline__ float sigf(float x){ return 1.f/(1.f+__expf(-x)); }
__device__ __forceinline__ uint32_t smem_u32(const void* p){
    uint32_t a;
    asm("{ .reg .u64 t; cvta.to.shared.u64 t, %1; cvt.u32.u64 %0, t; }":"=r"(a):"l"(p));
    return a;
}
__device__ __forceinline__ void ldmx4(uint32_t* r, uint32_t addr){
    asm volatile("ldmatrix.sync.aligned.m8n8.x4.shared.b16 {%0,%1,%2,%3},[%4];"
        :"=r"(r[0]),"=r"(r[1]),"=r"(r[2]),"=r"(r[3]):"r"(addr));
}
__device__ __forceinline__ void mma_f16(float* c, const uint32_t* a, const uint32_t* b){
    asm volatile("mma.sync.aligned.m16n8k16.row.col.f32.f16.f16.f32 "
        "{%0,%1,%2,%3},{%4,%5,%6,%7},{%8,%9},{%0,%1,%2,%3};"
        :"+f"(c[0]),"+f"(c[1]),"+f"(c[2]),"+f"(c[3])
        :"r"(a[0]),"r"(a[1]),"r"(a[2]),"r"(a[3]),"r"(b[0]),"r"(b[1]));
}

__global__ void k_zero(){
    size_t st=(size_t)gridDim.x*blockDim.x;
    for(size_t i=(size_t)blockIdx.x*blockDim.x+threadIdx.x; i<CTXN+CNTN; i+=st){
        if(i<CTXN) g_ctx[i]=0.f; else g_cnt[i-CTXN]=0.f;
    }
    if(blockIdx.x==0 && threadIdx.x<Bn) g_umax[threadIdx.x]=0;
}

__global__ void k_prep(const float* __restrict__ uvs, const float* __restrict__ msk,
                       const float* __restrict__ wg, const float* __restrict__ wb,
                       const float* __restrict__ wh){
    int i=blockIdx.x*blockDim.x+threadIdx.x;
    if(i>=Bn*Vn*HWn) return;
    float u=uvs[2*i], v=uvs[2*i+1];
    bool fin=isfinite(u)&&isfinite(v);
    float su=fin?u:0.f, sv=fin?v:0.f;
    int xi=(int)rintf(fminf(fmaxf(su,0.f),1.f)*(float)(An-1));
    int yi=(int)rintf((1.f-fminf(fmaxf(sv,0.f),1.f))*(float)(An-1));
    g_idx[i]=yi*An+xi;
    bool mv=(msk[i]>0.5f)&&fin;
    int bv=i/HWn;
    float w0=fmaxf(wg[bv],0.f), w1=fmaxf(wb[bv],0.f), w2=fmaxf(wh[bv],0.f);
    g_wts[0][i]=(mv&&w0>0.f)?w0:0.f;
    g_wts[1][i]=(mv&&w1>0.f)?w1:0.f;
    g_wts[2][i]=(mv&&w2>0.f)?w2:0.f;
}

__global__ void k_scatter(const float* __restrict__ vf){
    int bv=blockIdx.y;
    int px=blockIdx.x*blockDim.x+threadIdx.x;
    int i=bv*HWn+px;
    int b=bv>>3;
    int idx=g_idx[i];
    float w0=g_wts[0][i], w1=g_wts[1][i], w2=g_wts[2][i];
    if(w0<=0.f && w1<=0.f && w2<=0.f) return;
    float* base=g_ctx+(size_t)b*C3n*Pn+idx;
    const float* vp=vf+(size_t)bv*Cn*HWn+px;
    #pragma unroll 4
    for(int c=0;c<Cn;c++){
        float v=vp[(size_t)c*HWn];
        if(w0>0.f) atomicAdd(base+(size_t)c*Pn, w0*v);
        if(w1>0.f) atomicAdd(base+(size_t)(Cn+c)*Pn, w1*v);
        if(w2>0.f) atomicAdd(base+(size_t)(2*Cn+c)*Pn, w2*v);
    }
    if(w0>0.f) atomicAdd(&g_cnt[((size_t)b*3+0)*Pn+idx], w0);
    if(w1>0.f) atomicAdd(&g_cnt[((size_t)b*3+1)*Pn+idx], w1);
    if(w2>0.f) atomicAdd(&g_cnt[((size_t)b*3+2)*Pn+idx], w2);
}

__global__ void k_finalize(){
    int i=blockIdx.x*blockDim.x+threadIdx.x;
    int b=i>>16, px=i&(Pn-1);
    size_t base=(size_t)b*C3n*Pn+px;
    float c0=g_cnt[((size_t)b*3+0)*Pn+px];
    float c1=g_cnt[((size_t)b*3+1)*Pn+px];
    float c2=g_cnt[((size_t)b*3+2)*Pn+px];
    float i0=1.f/fmaxf(c0,1.f), i1=1.f/fmaxf(c1,1.f), i2=1.f/fmaxf(c2,1.f);
    float ss=0.f;
    #pragma unroll 4
    for(int c=0;c<Cn;c++){
        float g=g_ctx[base+(size_t)c*Pn]*i0;
        float h=g_ctx[base+(size_t)(Cn+c)*Pn]*i1;
        float t=g_ctx[base+(size_t)(2*Cn+c)*Pn]*i2;
        g_ctx[base+(size_t)c*Pn]=g;
        g_ctx[base+(size_t)(Cn+c)*Pn]=h;
        g_ctx[base+(size_t)(2*Cn+c)*Pn]=t;
        float m=(g+h+t)*(1.f/3.f);
        float dg=g-m, dh=h-m, dt=t-m;
        ss+=dg*dg+dh*dh+dt*dt;
    }
    float cov=((c0>0.f?1.f:0.f)+(c1>0.f?1.f:0.f)+(c2>0.f?1.f:0.f))*(1.f/3.f);
    cov=fminf(cov,1.f);
    float uraw=sqrtf(ss*(1.f/(3.f*Cn)));
    g_ctx[base+(size_t)192*Pn]=cov;
    g_uraw[i]=uraw;
    float m=uraw;
    #pragma unroll
    for(int o=16;o>0;o>>=1) m=fmaxf(m,__shfl_xor_sync(0xffffffffu,m,o));
    if((threadIdx.x&31)==0) atomicMax(&g_umax[b], __float_as_int(m));
}

__global__ void k_uncert(float* __restrict__ dout){
    int i=blockIdx.x*blockDim.x+threadIdx.x;
    int b=i>>16, px=i&(Pn-1);
    size_t base=(size_t)b*C3n*Pn+px;
    float cov=g_ctx[base+(size_t)192*Pn];
    float sc=fmaxf(__int_as_float(g_umax[b]),1e-6f);
    float un=fminf(fmaxf(g_uraw[i]/sc,0.f),1.f)*cov;
    g_ctx[base+(size_t)193*Pn]=un;
    dout[OFF_COV+i]=cov;
    dout[OFF_UNC+i]=un;
}

// pack ctx -> fp16 channel-pair words
__global__ void k_cvt(){
    int px=blockIdx.x*blockDim.x+threadIdx.x;
    int c2=blockIdx.y, b=blockIdx.z;
    const float* p=g_ctx+((size_t)b*C3n+2*c2)*Pn+px;
    __half2 h=__floats2half2_rn(p[0],p[Pn]);
    g_ctxh[((size_t)b*112+c2)*Pn+px]=*reinterpret_cast<uint32_t*>(&h);
}

// weights -> fp16 [grp][co 192][104k]; grp=(dy,cib); k=dx*32+ci_local
template<int MODE,int CIB>
__global__ void k_wtrans(const float* __restrict__ w){
    constexpr int CIN =(MODE==0)?C3n:COn;
    constexpr int NG  =3*CIB;
    int n=NG*192*BROW;
    int i=blockIdx.x*blockDim.x+threadIdx.x;
    if(i>=n) return;
    int grp=i/(192*BROW);
    int r=i-grp*(192*BROW);
    int co=r/BROW, k=r-co*BROW;
    float v=0.f;
    if(k<96){
        int dy=grp/CIB, cib=grp-dy*CIB;
        int dx=k>>5, ci=cib*32+(k&31);
        int tap=dy*3+dx;
        v=(ci<CIN)?w[((size_t)co*CIN+ci)*9+tap]:0.f;
    }
    unsigned short hv=__half_as_ushort(__float2half_rn(v));
    if(MODE==0) g_wTc1h[i]=hv; else g_wTc2h[i]=hv;
}

// ---------------- fp16 mma.sync conv, K=96 macro-chunks, 3-stage pipeline ----------------
// A: pair-packed window [16 ci2][152 pitch (144 px)] b32, x3 buffers
// B: fp16 [96 co][104 k], x3 buffers
constexpr int SMA=9728;           // 16*152*4
constexpr int SMBb=19968;         // 96*104*2
constexpr int SMB0b=3*SMA;        // 29184
constexpr int SM_BYTES=SMB0b+3*SMBb;  // 89088

template<int CI2,int CI2P,int CIB,int MODE>
__global__ void __launch_bounds__(256,2) k_mconv(const float* __restrict__ bias){
    constexpr int NG=3*CIB;
    extern __shared__ __align__(1024) char smem[];
    const uint32_t* inH=(MODE==0)?g_ctxh:g_h1h;
    const unsigned short* wT=(MODE==0)?g_wTc1h:g_wTc2h;
    float* out=(MODE==0)?g_h1:g_h2;
    const int tid=threadIdx.x, wid=tid>>5, lane=tid&31;
    const int sb=blockIdx.x, cn=blockIdx.y, b=blockIdx.z;
    const int y=sb>>1, x0=(sb&1)*128;
    const uint32_t* inB=inH+(size_t)b*CI2P*Pn;
    const uint32_t sbase=smem_u32(smem);
    const uint32_t* Aw=(const uint32_t*)smem;

    // warp layout: 4 M-warps x 2 N-warps; warp tile 32m x 48n
    const int wm=wid&3, wn=wid>>2;
    const int g=lane>>2, tig=lane&3;
    const int nrow=(lane&7)+((lane>>4)<<3);
    const uint32_t blane=(uint32_t)(nrow*208+((lane&8)?16:0));

    float acc[2][6][4];
    #pragma unroll
    for(int mt=0;mt<2;mt++)
        #pragma unroll
        for(int nt=0;nt<6;nt++)
            #pragma unroll
            for(int q=0;q<4;q++) acc[mt][nt][q]=0.f;

    auto prefA=[&](int grp,int buf){
        int dy=grp/CIB, cib=grp-dy*CIB;
        int gy=y+dy-1;
        bool rok=((unsigned)gy<256u);
        uint32_t ab=sbase+(uint32_t)buf*SMA;
        #pragma unroll 1
        for(int l=tid;l<576;l+=256){
            int ci=l/36, v=l-ci*36;          // 36 16B-chunks per row (144 px)
            int ci2g=cib*16+ci;
            int px0=x0-8+4*v;
            bool ok=rok&&(ci2g<CI2)&&((unsigned)px0<253u);
            const uint32_t* src=inB+(size_t)(ok?ci2g:0)*Pn+(ok?(gy*256+px0):0);
            unsigned sz=ok?16u:0u;
            asm volatile("cp.async.cg.shared.global [%0],[%1],16,%2;"
                ::"r"(ab+(uint32_t)(ci*152+4*v)*4u),"l"(src),"r"(sz));
        }
    };
    auto prefB=[&](int grp,int buf){
        const float4* ws=(const float4*)(wT+(size_t)grp*(192*BROW)+(size_t)cn*(96*BROW));
        uint32_t bd=sbase+SMB0b+(uint32_t)buf*SMBb;
        #pragma unroll 1
        for(int l=tid;l<1248;l+=256)
            asm volatile("cp.async.cg.shared.global [%0],[%1],16;"
                ::"r"(bd+(uint32_t)l*16u),"l"(ws+l));
    };

    prefA(0,0); prefB(0,0);
    asm volatile("cp.async.commit_group;");
    prefA(1,1); prefB(1,1);
    asm volatile("cp.async.commit_group;");

    #pragma unroll 1
    for(int grp=0;grp<NG;grp++){
        if(grp<NG-1) asm volatile("cp.async.wait_group 1;");
        else         asm volatile("cp.async.wait_group 0;");
        __syncthreads();
        if(grp+2<NG){
            int nb=(grp+2)%3;
            prefA(grp+2,nb);
            prefB(grp+2,nb);
            asm volatile("cp.async.commit_group;");
        }
        const int buf=grp%3;
        const uint32_t* As=Aw+buf*(SMA/4);
        const uint32_t bbase=sbase+SMB0b+(uint32_t)buf*SMBb+blane;
        #pragma unroll
        for(int kk=0;kk<6;kk++){
            const int dx=kk>>1;
            uint32_t bf[3][4];
            #pragma unroll
            for(int p=0;p<3;p++)
                ldmx4(bf[p], bbase+(uint32_t)((wn*48+p*16)*208)+(uint32_t)(kk*32));
            const int arow=((kk&1)*8+tig)*152;
            const int pxo=dx+7+g;
            #pragma unroll
            for(int mt=0;mt<2;mt++){
                uint32_t af[4];
                int ab=arow+wm*32+mt*16+pxo;
                af[0]=As[ab];
                af[1]=As[ab+8];
                af[2]=As[ab+4*152];
                af[3]=As[ab+4*152+8];
                #pragma unroll
                for(int nt=0;nt<6;nt++)
                    mma_f16(acc[mt][nt], af, &bf[nt>>1][(nt&1)*2]);
            }
        }
    }

    // epilogue
    const int row0=wm*32+(lane>>2);
    const int col0=cn*96+wn*48+2*(lane&3);
    const size_t pxb=(size_t)y*256+x0;
    #pragma unroll
    for(int mt=0;mt<2;mt++){
        int r0=row0+mt*16;
        #pragma unroll
        for(int nt=0;nt<6;nt++){
            int co=col0+nt*8;
            float b0=__ldg(bias+co), b1=__ldg(bias+co+1);
            float* o0=out+(size_t)(b*COn+co)*Pn+pxb;
            float* o1=o0+Pn;
            o0[r0]   =acc[mt][nt][0]+b0;
            o1[r0]   =acc[mt][nt][1]+b1;
            o0[r0+8] =acc[mt][nt][2]+b0;
            o1[r0+8] =acc[mt][nt][3]+b1;
        }
    }
}

template<int MODE>
__global__ void k_chansum(){
    __shared__ float ss[256], sq[256];
    const float* x=(MODE==0)?g_h1:g_h2;
    int bc=blockIdx.x;
    const float* p=x+(size_t)bc*Pn;
    float s=0.f,q=0.f;
    for(int i=threadIdx.x;i<Pn;i+=256){ float v=p[i]; s+=v; q+=v*v; }
    ss[threadIdx.x]=s; sq[threadIdx.x]=q;
    __syncthreads();
    for(int st=128;st>0;st>>=1){
        if(threadIdx.x<st){ ss[threadIdx.x]+=ss[threadIdx.x+st]; sq[threadIdx.x]+=sq[threadIdx.x+st]; }
        __syncthreads();
    }
    if(threadIdx.x==0){ g_csum[bc*2]=ss[0]; g_csum[bc*2+1]=sq[0]; }
}

__global__ void k_stats(const float* __restrict__ scale, const float* __restrict__ shift){
    __shared__ float gm[16], gr[16];
    int t=threadIdx.x;
    if(t<Bn*8){
        int b=t/8, g=t%8;
        float s=0.f,q=0.f;
        for(int c=0;c<24;c++){
            s+=g_csum[(b*COn+g*24+c)*2];
            q+=g_csum[(b*COn+g*24+c)*2+1];
        }
        float N=24.f*(float)Pn;
        float mean=s/N;
        float var=q/N-mean*mean;
        gm[t]=mean;
        gr[t]=rsqrtf(var+1e-5f);
    }
    __syncthreads();
    if(t<Bn*COn){
        int b=t/COn, c=t%COn, g=c/24;
        float a=gr[b*8+g]*scale[c];
        g_sA[t]=a;
        g_sB[t]=shift[c]-gm[b*8+g]*a;
    }
}

// GN1 + SiLU, emit fp16 pair-packed h1
__global__ void k_apply1(){
    int px=blockIdx.x*blockDim.x+threadIdx.x;
    int c2=blockIdx.y, b=blockIdx.z;
    int bc=b*COn+2*c2;
    const float* p=g_h1+(size_t)bc*Pn+px;
    float v0=siluf(p[0]*g_sA[bc]+g_sB[bc]);
    float v1=siluf(p[Pn]*g_sA[bc+1]+g_sB[bc+1]);
    __half2 h=__floats2half2_rn(v0,v1);
    g_h1h[((size_t)b*96+c2)*Pn+px]=*reinterpret_cast<uint32_t*>(&h);
}

__global__ void k_poolsum(){
    __shared__ float red[256];
    int bc=blockIdx.x;
    const float* p=g_h2+(size_t)bc*Pn;
    float a=g_sA[bc], s0=g_sB[bc];
    float s=0.f;
    for(int i=threadIdx.x;i<Pn;i+=256) s+=siluf(p[i]*a+s0);
    red[threadIdx.x]=s;
    __syncthreads();
    for(int st=128;st>0;st>>=1){
        if(threadIdx.x<st) red[threadIdx.x]+=red[threadIdx.x+st];
        __syncthreads();
    }
    if(threadIdx.x==0) g_pool[bc]=red[0];
}

__global__ void k_gate(const float* __restrict__ gw1, const float* __restrict__ gb1,
                       const float* __restrict__ gw2, const float* __restrict__ gb2){
    __shared__ float pooled[COn];
    __shared__ float hbuf[HIDn];
    for(int b=0;b<Bn;b++){
        for(int c=threadIdx.x;c<COn;c+=blockDim.x)
            pooled[c]=g_pool[b*COn+c]*(1.f/(float)Pn);
        __syncthreads();
        if(threadIdx.x<HIDn){
            float s=gb1[threadIdx.x];
            for(int c=0;c<COn;c++) s+=gw1[threadIdx.x*COn+c]*pooled[c];
            hbuf[threadIdx.x]=siluf(s);
        }
        __syncthreads();
        if(threadIdx.x<COn){
            float s=gb2[threadIdx.x];
            for(int j=0;j<HIDn;j++) s+=gw2[threadIdx.x*HIDn+j]*hbuf[j];
            g_gate[b*COn+threadIdx.x]=0.5f+sigf(s);
        }
        __syncthreads();
    }
}

__device__ __forceinline__ ull pack2(float v){ ull r; asm("mov.b64 %0,{%1,%1};":"=l"(r):"f"(v)); return r; }
__device__ __forceinline__ void fma2(ull&a, ull x, ull w){ asm("fma.rn.f32x2 %0,%1,%2,%0;":"+l"(a):"l"(x),"l"(w)); }
__device__ __forceinline__ void unpack2(ull v, float&lo, float&hi){ asm("mov.b64 {%0,%1},%2;":"=f"(lo),"=f"(hi):"l"(v)); }

// residual 1x1 + inline confidence + GN2/SiLU + gate + mix -> outputs
__global__ void __launch_bounds__(256) k_res_combine(
    const float* __restrict__ rpw, const float* __restrict__ rpb,
    const float* __restrict__ prs, const float* __restrict__ pmix,
    const float* __restrict__ cfw, const float* __restrict__ cfb,
    float* __restrict__ dout){
    __shared__ __align__(16) float s_w[97*64];
    __shared__ float s_cwb[97];
    __shared__ float s_sA[64], s_sB[64], s_g[64];
    const int br=blockIdx.y, b=blockIdx.z;
    const int og=threadIdx.x>>6, pl=threadIdx.x&63;
    const int pxb=blockIdx.x*256;
    const float* ctxb=g_ctx+(size_t)b*C3n*Pn;

    if(threadIdx.x<64){
        int bc=b*COn+br*64+threadIdx.x;
        s_sA[threadIdx.x]=g_sA[bc];
        s_sB[threadIdx.x]=g_sB[bc];
        s_g[threadIdx.x]=g_gate[bc];
    }

    ull acc[4][8];
    #pragma unroll
    for(int k=0;k<4;k++)
        #pragma unroll
        for(int j=0;j<8;j++) acc[k][j]=0;
    float cf[4]={0.f,0.f,0.f,0.f};

    #pragma unroll 1
    for(int half=0;half<2;half++){
        int ci0=half*97;
        for(int l=threadIdx.x;l<97*64;l+=256){
            int ci=l>>6, o=l&63;
            s_w[l]=rpw[(size_t)(br*64+o)*C3n+ci0+ci];
        }
        if(threadIdx.x<97) s_cwb[threadIdx.x]=cfw[br*C3n+ci0+threadIdx.x];
        __syncthreads();
        #pragma unroll 1
        for(int ci=0;ci<97;ci++){
            const float* xp=ctxb+(size_t)(ci0+ci)*Pn+pxb+pl;
            float x0=xp[0], x1=xp[64], x2=xp[128], x3=xp[192];
            float wv=s_cwb[ci];
            cf[0]+=x0*wv; cf[1]+=x1*wv; cf[2]+=x2*wv; cf[3]+=x3*wv;
            ull p0=pack2(x0), p1=pack2(x1), p2=pack2(x2), p3=pack2(x3);
            const ull* wrow=reinterpret_cast<const ull*>(s_w+ci*64+og*16);
            #pragma unroll
            for(int j=0;j<8;j++){
                ull w=wrow[j];
                fma2(acc[0][j],p0,w); fma2(acc[1][j],p1,w);
                fma2(acc[2][j],p2,w); fma2(acc[3][j],p3,w);
            }
        }
        __syncthreads();
    }

    const float trs=tanhf(prs[0]);
    const float ms=tanhf(pmix[0]);
    const float cb=cfb[br];
    #pragma unroll
    for(int k=0;k<4;k++){
        int px=pxb+pl+k*64;
        float confv=sigf(cf[k]+cb);
        dout[OFF_CONF+((size_t)(b*3+br))*Pn+px]=confv;
        #pragma unroll
        for(int j=0;j<8;j++){
            float lo,hi; unpack2(acc[k][j],lo,hi);
            #pragma unroll
            for(int half=0;half<2;half++){
                int c=og*16+2*j+half;
                int co=br*64+c;
                float res=(half?hi:lo)+rpb[co];
                float hraw=g_h2[((size_t)(b*COn)+co)*Pn+px];
                float h=siluf(hraw*s_sA[c]+s_sB[c]);
                float refine=h*s_g[c]+trs*res;
                float feat=ctxb[(size_t)co*Pn+px];
                dout[(size_t)br*((size_t)Bn*Cn*Pn)+((size_t)(b*Cn+c))*Pn+px]
                    =feat+ms*refine*confv;
            }
        }
    }
}

extern "C" void kernel_launch(void* const* d_in, const int* in_sizes, int n_in,
                              void* d_out, int out_size){
    const float* vf   =(const float*)d_in[0];
    const float* uvs  =(const float*)d_in[1];
    const float* msk  =(const float*)d_in[2];
    const float* wg   =(const float*)d_in[3];
    const float* wb   =(const float*)d_in[4];
    const float* wh   =(const float*)d_in[5];
    const float* c1w  =(const float*)d_in[7];
    const float* c1b  =(const float*)d_in[8];
    const float* g1s  =(const float*)d_in[9];
    const float* g1b  =(const float*)d_in[10];
    const float* c2w  =(const float*)d_in[11];
    const float* c2b  =(const float*)d_in[12];
    const float* g2s  =(const float*)d_in[13];
    const float* g2b  =(const float*)d_in[14];
    const float* gw1  =(const float*)d_in[15];
    const float* gb1  =(const float*)d_in[16];
    const float* gw2  =(const float*)d_in[17];
    const float* gb2  =(const float*)d_in[18];
    const float* rpw  =(const float*)d_in[19];
    const float* rpb  =(const float*)d_in[20];
    const float* rs   =(const float*)d_in[21];
    const float* cfw  =(const float*)d_in[22];
    const float* cfb  =(const float*)d_in[23];
    const float* mixs =(const float*)d_in[24];
    float* dout=(float*)d_out;

    static int smem_set=0;
    if(!smem_set){
        cudaFuncSetAttribute(k_mconv<97,112,7,0>,
            cudaFuncAttributeMaxDynamicSharedMemorySize, SM_BYTES);
        cudaFuncSetAttribute(k_mconv<96,96,6,1>,
            cudaFuncAttributeMaxDynamicSharedMemorySize, SM_BYTES);
        cudaFuncSetAttribute(k_mconv<97,112,2,0>,
            cudaFuncAttributeMaxDynamicSharedMemorySize, SM_BYTES);
        smem_set=1;
    }

    k_zero<<<512,256>>>();                                          // 0
    k_prep<<<1024,256>>>(uvs,msk,wg,wb,wh);                         // 1
    k_scatter<<<dim3(64,16),256>>>(vf);                             // 2
    // PROBE: same conv kernel at occupancy 2 (296 CTAs), 6 steady-state
    // groups; outputs fully overwritten by the real conv1 (profiling slot 3).
    k_mconv<97,112,2,0><<<dim3(148,2,1),256,SM_BYTES>>>(c1b);       // 3
    k_finalize<<<512,256>>>();                                      // 4
    k_wtrans<0,7><<<(NG1*192*BROW+255)/256,256>>>(c1w);             // 5
    k_wtrans<1,6><<<(NG2*192*BROW+255)/256,256>>>(c2w);             // 6
    k_uncert<<<512,256>>>(dout);                                    // 7
    k_cvt<<<dim3(256,97,2),256>>>();                                // 8
    k_mconv<97,112,7,0><<<dim3(512,2,Bn),256,SM_BYTES>>>(c1b);      // 9
    k_chansum<0><<<Bn*COn,256>>>();                                 // 10
    k_stats<<<1,384>>>(g1s,g1b);                                    // 11
    k_apply1<<<dim3(256,96,2),256>>>();                             // 12
    k_mconv<96,96,6,1><<<dim3(512,2,Bn),256,SM_BYTES>>>(c2b);       // 13
    k_chansum<1><<<Bn*COn,256>>>();                                 // 14
    k_stats<<<1,384>>>(g2s,g2b);                                    // 15
    k_poolsum<<<Bn*COn,256>>>();                                    // 16
    k_gate<<<1,192>>>(gw1,gb1,gw2,gb2);                             // 17
    k_res_combine<<<dim3(256,3,2),256>>>(rpw,rpb,rs,mixs,cfw,cfb,dout); // 18
}

// round 15
// speedup vs baseline: 1.0090x; 1.0090x over previous
#include <cuda_runtime.h>
#include <cuda_fp16.h>
#include <math.h>
#include <stdint.h>

typedef unsigned long long ull;

constexpr int Bn=2, Vn=8, Cn=64, An=256;
constexpr int HWn=128*128, Pn=An*An;
constexpr int C3n=194, COn=192, HIDn=48;

constexpr size_t CTXN=(size_t)Bn*C3n*Pn;
constexpr size_t CNTN=(size_t)Bn*3*Pn;
constexpr size_t OFF_COV =(size_t)3*Bn*Cn*Pn;
constexpr size_t OFF_UNC =OFF_COV+(size_t)Bn*Pn;
constexpr size_t OFF_CONF=OFF_UNC+(size_t)Bn*Pn;

constexpr int NG1=21;    // 3 dy * 7 cib   (K=96 per group: 3dx x 32ci)
constexpr int NG2=18;    // 3 dy * 6 cib
constexpr int BROW=104;  // B row pitch in halfwords

__device__ float  g_ctx[CTXN];
__device__ float  g_cnt[CNTN];
__device__ float  g_uraw[(size_t)Bn*Pn];
__device__ int    g_umax[Bn];
__device__ int    g_idx[Bn*Vn*HWn];
__device__ float  g_wts[3][Bn*Vn*HWn];
__device__ float  g_h1[(size_t)Bn*COn*Pn];
__device__ float  g_h2[(size_t)Bn*COn*Pn];
__device__ uint32_t g_ctxh[(size_t)Bn*112*Pn];
__device__ uint32_t g_h1h [(size_t)Bn*96*Pn];
__device__ unsigned short g_wTc1h[NG1*192*BROW];
__device__ unsigned short g_wTc2h[NG2*192*BROW];
__device__ float  g_csum[Bn*COn*2];
__device__ float  g_sA[Bn*COn], g_sB[Bn*COn];
__device__ float  g_gate[Bn*COn];
__device__ float  g_pool[Bn*COn];

__device__ __forceinline__ float siluf(float x){ return x/(1.f+__expf(-x)); }
__device__ __forceinline__ float sigf(float x){ return 1.f/(1.f+__expf(-x)); }
__device__ __forceinline__ uint32_t smem_u32(const void* p){
    uint32_t a;
    asm("{ .reg .u64 t; cvta.to.shared.u64 t, %1; cvt.u32.u64 %0, t; }":"=r"(a):"l"(p));
    return a;
}
__device__ __forceinline__ void ldmx4(uint32_t* r, uint32_t addr){
    asm volatile("ldmatrix.sync.aligned.m8n8.x4.shared.b16 {%0,%1,%2,%3},[%4];"
        :"=r"(r[0]),"=r"(r[1]),"=r"(r[2]),"=r"(r[3]):"r"(addr));
}
__device__ __forceinline__ void mma_f16(float* c, const uint32_t* a, const uint32_t* b){
    asm volatile("mma.sync.aligned.m16n8k16.row.col.f32.f16.f16.f32 "
        "{%0,%1,%2,%3},{%4,%5,%6,%7},{%8,%9},{%0,%1,%2,%3};"
        :"+f"(c[0]),"+f"(c[1]),"+f"(c[2]),"+f"(c[3])
        :"r"(a[0]),"r"(a[1]),"r"(a[2]),"r"(a[3]),"r"(b[0]),"r"(b[1]));
}
__device__ __forceinline__ uint32_t packh2(float lo, float hi){
    __half2 h=__floats2half2_rn(lo,hi);
    return *reinterpret_cast<uint32_t*>(&h);
}

__global__ void k_zero(){
    size_t st=(size_t)gridDim.x*blockDim.x;
    for(size_t i=(size_t)blockIdx.x*blockDim.x+threadIdx.x; i<CTXN+CNTN; i+=st){
        if(i<CTXN) g_ctx[i]=0.f; else g_cnt[i-CTXN]=0.f;
    }
    if(blockIdx.x==0 && threadIdx.x<Bn) g_umax[threadIdx.x]=0;
}

__global__ void k_prep(const float* __restrict__ uvs, const float* __restrict__ msk,
                       const float* __restrict__ wg, const float* __restrict__ wb,
                       const float* __restrict__ wh){
    int i=blockIdx.x*blockDim.x+threadIdx.x;
    if(i>=Bn*Vn*HWn) return;
    float u=uvs[2*i], v=uvs[2*i+1];
    bool fin=isfinite(u)&&isfinite(v);
    float su=fin?u:0.f, sv=fin?v:0.f;
    int xi=(int)rintf(fminf(fmaxf(su,0.f),1.f)*(float)(An-1));
    int yi=(int)rintf((1.f-fminf(fmaxf(sv,0.f),1.f))*(float)(An-1));
    g_idx[i]=yi*An+xi;
    bool mv=(msk[i]>0.5f)&&fin;
    int bv=i/HWn;
    float w0=fmaxf(wg[bv],0.f), w1=fmaxf(wb[bv],0.f), w2=fmaxf(wh[bv],0.f);
    g_wts[0][i]=(mv&&w0>0.f)?w0:0.f;
    g_wts[1][i]=(mv&&w1>0.f)?w1:0.f;
    g_wts[2][i]=(mv&&w2>0.f)?w2:0.f;
}

__global__ void k_scatter(const float* __restrict__ vf){
    int bv=blockIdx.y;
    int px=blockIdx.x*blockDim.x+threadIdx.x;
    int i=bv*HWn+px;
    int b=bv>>3;
    int idx=g_idx[i];
    float w0=g_wts[0][i], w1=g_wts[1][i], w2=g_wts[2][i];
    if(w0<=0.f && w1<=0.f && w2<=0.f) return;
    float* base=g_ctx+(size_t)b*C3n*Pn+idx;
    const float* vp=vf+(size_t)bv*Cn*HWn+px;
    #pragma unroll 4
    for(int c=0;c<Cn;c++){
        float v=vp[(size_t)c*HWn];
        if(w0>0.f) atomicAdd(base+(size_t)c*Pn, w0*v);
        if(w1>0.f) atomicAdd(base+(size_t)(Cn+c)*Pn, w1*v);
        if(w2>0.f) atomicAdd(base+(size_t)(2*Cn+c)*Pn, w2*v);
    }
    if(w0>0.f) atomicAdd(&g_cnt[((size_t)b*3+0)*Pn+idx], w0);
    if(w1>0.f) atomicAdd(&g_cnt[((size_t)b*3+1)*Pn+idx], w1);
    if(w2>0.f) atomicAdd(&g_cnt[((size_t)b*3+2)*Pn+idx], w2);
}

// normalize atlas, coverage, raw uncertainty + emit fp16 pair-packed ctx
__global__ void k_finalize(){
    int i=blockIdx.x*blockDim.x+threadIdx.x;
    int b=i>>16, px=i&(Pn-1);
    size_t base=(size_t)b*C3n*Pn+px;
    size_t hbase=(size_t)b*112*Pn+px;
    float c0=g_cnt[((size_t)b*3+0)*Pn+px];
    float c1=g_cnt[((size_t)b*3+1)*Pn+px];
    float c2=g_cnt[((size_t)b*3+2)*Pn+px];
    float i0=1.f/fmaxf(c0,1.f), i1=1.f/fmaxf(c1,1.f), i2=1.f/fmaxf(c2,1.f);
    float ss=0.f;
    #pragma unroll 4
    for(int c2i=0;c2i<32;c2i++){
        int c=2*c2i;
        float ga=g_ctx[base+(size_t)c*Pn]*i0;
        float gb=g_ctx[base+(size_t)(c+1)*Pn]*i0;
        float ha=g_ctx[base+(size_t)(Cn+c)*Pn]*i1;
        float hb=g_ctx[base+(size_t)(Cn+c+1)*Pn]*i1;
        float ta=g_ctx[base+(size_t)(2*Cn+c)*Pn]*i2;
        float tb=g_ctx[base+(size_t)(2*Cn+c+1)*Pn]*i2;
        g_ctx[base+(size_t)c*Pn]=ga;
        g_ctx[base+(size_t)(c+1)*Pn]=gb;
        g_ctx[base+(size_t)(Cn+c)*Pn]=ha;
        g_ctx[base+(size_t)(Cn+c+1)*Pn]=hb;
        g_ctx[base+(size_t)(2*Cn+c)*Pn]=ta;
        g_ctx[base+(size_t)(2*Cn+c+1)*Pn]=tb;
        g_ctxh[hbase+(size_t)c2i*Pn]      =packh2(ga,gb);
        g_ctxh[hbase+(size_t)(32+c2i)*Pn] =packh2(ha,hb);
        g_ctxh[hbase+(size_t)(64+c2i)*Pn] =packh2(ta,tb);
        float ma=(ga+ha+ta)*(1.f/3.f);
        float mb=(gb+hb+tb)*(1.f/3.f);
        float d0=ga-ma,d1=ha-ma,d2=ta-ma,d3=gb-mb,d4=hb-mb,d5=tb-mb;
        ss+=d0*d0+d1*d1+d2*d2+d3*d3+d4*d4+d5*d5;
    }
    float cov=((c0>0.f?1.f:0.f)+(c1>0.f?1.f:0.f)+(c2>0.f?1.f:0.f))*(1.f/3.f);
    cov=fminf(cov,1.f);
    float uraw=sqrtf(ss*(1.f/(3.f*Cn)));
    g_ctx[base+(size_t)192*Pn]=cov;
    g_uraw[i]=uraw;
    float m=uraw;
    #pragma unroll
    for(int o=16;o>0;o>>=1) m=fmaxf(m,__shfl_xor_sync(0xffffffffu,m,o));
    if((threadIdx.x&31)==0) atomicMax(&g_umax[b], __float_as_int(m));
}

__global__ void k_uncert(float* __restrict__ dout){
    int i=blockIdx.x*blockDim.x+threadIdx.x;
    int b=i>>16, px=i&(Pn-1);
    size_t base=(size_t)b*C3n*Pn+px;
    float cov=g_ctx[base+(size_t)192*Pn];
    float sc=fmaxf(__int_as_float(g_umax[b]),1e-6f);
    float un=fminf(fmaxf(g_uraw[i]/sc,0.f),1.f)*cov;
    g_ctx[base+(size_t)193*Pn]=un;
    g_ctxh[((size_t)b*112+96)*Pn+px]=packh2(cov,un);
    dout[OFF_COV+i]=cov;
    dout[OFF_UNC+i]=un;
}

// weights -> fp16 [grp][co 192][104k]; grp=(dy,cib); k=dx*32+ci_local
template<int MODE,int CIB>
__global__ void k_wtrans(const float* __restrict__ w){
    constexpr int CIN =(MODE==0)?C3n:COn;
    constexpr int NG  =3*CIB;
    int n=NG*192*BROW;
    int i=blockIdx.x*blockDim.x+threadIdx.x;
    if(i>=n) return;
    int grp=i/(192*BROW);
    int r=i-grp*(192*BROW);
    int co=r/BROW, k=r-co*BROW;
    float v=0.f;
    if(k<96){
        int dy=grp/CIB, cib=grp-dy*CIB;
        int dx=k>>5, ci=cib*32+(k&31);
        int tap=dy*3+dx;
        v=(ci<CIN)?w[((size_t)co*CIN+ci)*9+tap]:0.f;
    }
    unsigned short hv=__half_as_ushort(__float2half_rn(v));
    if(MODE==0) g_wTc1h[i]=hv; else g_wTc2h[i]=hv;
}

// ---------------- fp16 mma.sync conv, K=96 macro-chunks, 2-stage ----------------
constexpr int SMA=9728;           // 16*152*4
constexpr int SMBb=19968;         // 96*104*2
constexpr int SMB0b=2*SMA;        // 19456
constexpr int SM_BYTES=SMB0b+2*SMBb;  // 59392

template<int CI2,int CI2P,int CIB,int MODE>
__global__ void __launch_bounds__(256,2) k_mconv(const float* __restrict__ bias){
    constexpr int NG=3*CIB;
    extern __shared__ __align__(1024) char smem[];
    const uint32_t* inH=(MODE==0)?g_ctxh:g_h1h;
    const unsigned short* wT=(MODE==0)?g_wTc1h:g_wTc2h;
    float* out=(MODE==0)?g_h1:g_h2;
    const int tid=threadIdx.x, wid=tid>>5, lane=tid&31;
    const int sb=blockIdx.x, cn=blockIdx.y, b=blockIdx.z;
    const int y=sb>>1, x0=(sb&1)*128;
    const uint32_t* inB=inH+(size_t)b*CI2P*Pn;
    const uint32_t sbase=smem_u32(smem);
    const uint32_t* Aw=(const uint32_t*)smem;

    const int wm=wid&3, wn=wid>>2;
    const int g=lane>>2, tig=lane&3;
    const int nrow=(lane&7)+((lane>>4)<<3);
    const uint32_t blane=(uint32_t)(nrow*208+((lane&8)?16:0));

    float acc[2][6][4];
    #pragma unroll
    for(int mt=0;mt<2;mt++)
        #pragma unroll
        for(int nt=0;nt<6;nt++)
            #pragma unroll
            for(int q=0;q<4;q++) acc[mt][nt][q]=0.f;

    auto prefA=[&](int grp,int buf){
        int dy=grp/CIB, cib=grp-dy*CIB;
        int gy=y+dy-1;
        bool rok=((unsigned)gy<256u);
        uint32_t ab=sbase+(uint32_t)buf*SMA;
        #pragma unroll 1
        for(int l=tid;l<576;l+=256){
            int ci=l/36, v=l-ci*36;
            int ci2g=cib*16+ci;
            int px0=x0-8+4*v;
            bool ok=rok&&(ci2g<CI2)&&((unsigned)px0<253u);
            const uint32_t* src=inB+(size_t)(ok?ci2g:0)*Pn+(ok?(gy*256+px0):0);
            unsigned sz=ok?16u:0u;
            asm volatile("cp.async.cg.shared.global [%0],[%1],16,%2;"
                ::"r"(ab+(uint32_t)(ci*152+4*v)*4u),"l"(src),"r"(sz));
        }
    };
    auto prefB=[&](int grp,int buf){
        const float4* ws=(const float4*)(wT+(size_t)grp*(192*BROW)+(size_t)cn*(96*BROW));
        uint32_t bd=sbase+SMB0b+(uint32_t)buf*SMBb;
        #pragma unroll 1
        for(int l=tid;l<1248;l+=256)
            asm volatile("cp.async.cg.shared.global [%0],[%1],16;"
                ::"r"(bd+(uint32_t)l*16u),"l"(ws+l));
    };

    prefA(0,0); prefB(0,0);
    asm volatile("cp.async.commit_group;");

    #pragma unroll 1
    for(int grp=0;grp<NG;grp++){
        asm volatile("cp.async.wait_group 0;");
        __syncthreads();
        if(grp+1<NG){
            prefA(grp+1,(grp+1)&1);
            prefB(grp+1,(grp+1)&1);
            asm volatile("cp.async.commit_group;");
        }
        const int buf=grp&1;
        const uint32_t* As=Aw+buf*(SMA/4);
        const uint32_t bbase=sbase+SMB0b+(uint32_t)buf*SMBb+blane;
        #pragma unroll
        for(int kk=0;kk<6;kk++){
            const int dx=kk>>1;
            uint32_t bf[3][4];
            #pragma unroll
            for(int p=0;p<3;p++)
                ldmx4(bf[p], bbase+(uint32_t)((wn*48+p*16)*208)+(uint32_t)(kk*32));
            const int arow=((kk&1)*8+tig)*152;
            const int pxo=dx+7+g;
            #pragma unroll
            for(int mt=0;mt<2;mt++){
                uint32_t af[4];
                int ab=arow+wm*32+mt*16+pxo;
                af[0]=As[ab];
                af[1]=As[ab+8];
                af[2]=As[ab+4*152];
                af[3]=As[ab+4*152+8];
                #pragma unroll
                for(int nt=0;nt<6;nt++)
                    mma_f16(acc[mt][nt], af, &bf[nt>>1][(nt&1)*2]);
            }
        }
    }

    const int row0=wm*32+(lane>>2);
    const int col0=cn*96+wn*48+2*(lane&3);
    const size_t pxb=(size_t)y*256+x0;
    #pragma unroll
    for(int mt=0;mt<2;mt++){
        int r0=row0+mt*16;
        #pragma unroll
        for(int nt=0;nt<6;nt++){
            int co=col0+nt*8;
            float b0=__ldg(bias+co), b1=__ldg(bias+co+1);
            float* o0=out+(size_t)(b*COn+co)*Pn+pxb;
            float* o1=o0+Pn;
            o0[r0]   =acc[mt][nt][0]+b0;
            o1[r0]   =acc[mt][nt][1]+b1;
            o0[r0+8] =acc[mt][nt][2]+b0;
            o1[r0+8] =acc[mt][nt][3]+b1;
        }
    }
}

template<int MODE>
__global__ void k_chansum(){
    __shared__ float ss[256], sq[256];
    const float* x=(MODE==0)?g_h1:g_h2;
    int bc=blockIdx.x;
    const float* p=x+(size_t)bc*Pn;
    float s=0.f,q=0.f;
    for(int i=threadIdx.x;i<Pn;i+=256){ float v=p[i]; s+=v; q+=v*v; }
    ss[threadIdx.x]=s; sq[threadIdx.x]=q;
    __syncthreads();
    for(int st=128;st>0;st>>=1){
        if(threadIdx.x<st){ ss[threadIdx.x]+=ss[threadIdx.x+st]; sq[threadIdx.x]+=sq[threadIdx.x+st]; }
        __syncthreads();
    }
    if(threadIdx.x==0){ g_csum[bc*2]=ss[0]; g_csum[bc*2+1]=sq[0]; }
}

__global__ void k_stats(const float* __restrict__ scale, const float* __restrict__ shift){
    __shared__ float gm[16], gr[16];
    int t=threadIdx.x;
    if(t<Bn*8){
        int b=t/8, g=t%8;
        float s=0.f,q=0.f;
        for(int c=0;c<24;c++){
            s+=g_csum[(b*COn+g*24+c)*2];
            q+=g_csum[(b*COn+g*24+c)*2+1];
        }
        float N=24.f*(float)Pn;
        float mean=s/N;
        float var=q/N-mean*mean;
        gm[t]=mean;
        gr[t]=rsqrtf(var+1e-5f);
    }
    __syncthreads();
    if(t<Bn*COn){
        int b=t/COn, c=t%COn, g=c/24;
        float a=gr[b*8+g]*scale[c];
        g_sA[t]=a;
        g_sB[t]=shift[c]-gm[b*8+g]*a;
    }
}

__global__ void k_apply1(){
    int px=blockIdx.x*blockDim.x+threadIdx.x;
    int c2=blockIdx.y, b=blockIdx.z;
    int bc=b*COn+2*c2;
    const float* p=g_h1+(size_t)bc*Pn+px;
    float v0=siluf(p[0]*g_sA[bc]+g_sB[bc]);
    float v1=siluf(p[Pn]*g_sA[bc+1]+g_sB[bc+1]);
    g_h1h[((size_t)b*96+c2)*Pn+px]=packh2(v0,v1);
}

__global__ void k_poolsum(){
    __shared__ float red[256];
    int bc=blockIdx.x;
    const float* p=g_h2+(size_t)bc*Pn;
    float a=g_sA[bc], s0=g_sB[bc];
    float s=0.f;
    for(int i=threadIdx.x;i<Pn;i+=256) s+=siluf(p[i]*a+s0);
    red[threadIdx.x]=s;
    __syncthreads();
    for(int st=128;st>0;st>>=1){
        if(threadIdx.x<st) red[threadIdx.x]+=red[threadIdx.x+st];
        __syncthreads();
    }
    if(threadIdx.x==0) g_pool[bc]=red[0];
}

__global__ void k_gate(const float* __restrict__ gw1, const float* __restrict__ gb1,
                       const float* __restrict__ gw2, const float* __restrict__ gb2){
    __shared__ float pooled[COn];
    __shared__ float hbuf[HIDn];
    for(int b=0;b<Bn;b++){
        for(int c=threadIdx.x;c<COn;c+=blockDim.x)
            pooled[c]=g_pool[b*COn+c]*(1.f/(float)Pn);
        __syncthreads();
        if(threadIdx.x<HIDn){
            float s=gb1[threadIdx.x];
            for(int c=0;c<COn;c++) s+=gw1[threadIdx.x*COn+c]*pooled[c];
            hbuf[threadIdx.x]=siluf(s);
        }
        __syncthreads();
        if(threadIdx.x<COn){
            float s=gb2[threadIdx.x];
            for(int j=0;j<HIDn;j++) s+=gw2[threadIdx.x*HIDn+j]*hbuf[j];
            g_gate[b*COn+threadIdx.x]=0.5f+sigf(s);
        }
        __syncthreads();
    }
}

__device__ __forceinline__ ull pack2(float v){ ull r; asm("mov.b64 %0,{%1,%1};":"=l"(r):"f"(v)); return r; }
__device__ __forceinline__ void fma2(ull&a, ull x, ull w){ asm("fma.rn.f32x2 %0,%1,%2,%0;":"+l"(a):"l"(x),"l"(w)); }
__device__ __forceinline__ void unpack2(ull v, float&lo, float&hi){ asm("mov.b64 {%0,%1},%2;":"=f"(lo),"=f"(hi):"l"(v)); }

__global__ void __launch_bounds__(256) k_res_combine(
    const float* __restrict__ rpw, const float* __restrict__ rpb,
    const float* __restrict__ prs, const float* __restrict__ pmix,
    const float* __restrict__ cfw, const float* __restrict__ cfb,
    float* __restrict__ dout){
    __shared__ __align__(16) float s_w[97*64];
    __shared__ float s_cwb[97];
    __shared__ float s_sA[64], s_sB[64], s_g[64];
    const int br=blockIdx.y, b=blockIdx.z;
    const int og=threadIdx.x>>6, pl=threadIdx.x&63;
    const int pxb=blockIdx.x*256;
    const float* ctxb=g_ctx+(size_t)b*C3n*Pn;

    if(threadIdx.x<64){
        int bc=b*COn+br*64+threadIdx.x;
        s_sA[threadIdx.x]=g_sA[bc];
        s_sB[threadIdx.x]=g_sB[bc];
        s_g[threadIdx.x]=g_gate[bc];
    }

    ull acc[4][8];
    #pragma unroll
    for(int k=0;k<4;k++)
        #pragma unroll
        for(int j=0;j<8;j++) acc[k][j]=0;
    float cf[4]={0.f,0.f,0.f,0.f};

    #pragma unroll 1
    for(int half=0;half<2;half++){
        int ci0=half*97;
        for(int l=threadIdx.x;l<97*64;l+=256){
            int ci=l>>6, o=l&63;
            s_w[l]=rpw[(size_t)(br*64+o)*C3n+ci0+ci];
        }
        if(threadIdx.x<97) s_cwb[threadIdx.x]=cfw[br*C3n+ci0+threadIdx.x];
        __syncthreads();
        #pragma unroll 1
        for(int ci=0;ci<97;ci++){
            const float* xp=ctxb+(size_t)(ci0+ci)*Pn+pxb+pl;
            float x0=xp[0], x1=xp[64], x2=xp[128], x3=xp[192];
            float wv=s_cwb[ci];
            cf[0]+=x0*wv; cf[1]+=x1*wv; cf[2]+=x2*wv; cf[3]+=x3*wv;
            ull p0=pack2(x0), p1=pack2(x1), p2=pack2(x2), p3=pack2(x3);
            const ull* wrow=reinterpret_cast<const ull*>(s_w+ci*64+og*16);
            #pragma unroll
            for(int j=0;j<8;j++){
                ull w=wrow[j];
                fma2(acc[0][j],p0,w); fma2(acc[1][j],p1,w);
                fma2(acc[2][j],p2,w); fma2(acc[3][j],p3,w);
            }
        }
        __syncthreads();
    }

    const float trs=tanhf(prs[0]);
    const float ms=tanhf(pmix[0]);
    const float cb=cfb[br];
    #pragma unroll
    for(int k=0;k<4;k++){
        int px=pxb+pl+k*64;
        float confv=sigf(cf[k]+cb);
        dout[OFF_CONF+((size_t)(b*3+br))*Pn+px]=confv;
        #pragma unroll
        for(int j=0;j<8;j++){
            float lo,hi; unpack2(acc[k][j],lo,hi);
            #pragma unroll
            for(int half=0;half<2;half++){
                int c=og*16+2*j+half;
                int co=br*64+c;
                float res=(half?hi:lo)+rpb[co];
                float hraw=g_h2[((size_t)(b*COn)+co)*Pn+px];
                float h=siluf(hraw*s_sA[c]+s_sB[c]);
                float refine=h*s_g[c]+trs*res;
                float feat=ctxb[(size_t)co*Pn+px];
                dout[(size_t)br*((size_t)Bn*Cn*Pn)+((size_t)(b*Cn+c))*Pn+px]
                    =feat+ms*refine*confv;
            }
        }
    }
}

extern "C" void kernel_launch(void* const* d_in, const int* in_sizes, int n_in,
                              void* d_out, int out_size){
    const float* vf   =(const float*)d_in[0];
    const float* uvs  =(const float*)d_in[1];
    const float* msk  =(const float*)d_in[2];
    const float* wg   =(const float*)d_in[3];
    const float* wb   =(const float*)d_in[4];
    const float* wh   =(const float*)d_in[5];
    const float* c1w  =(const float*)d_in[7];
    const float* c1b  =(const float*)d_in[8];
    const float* g1s  =(const float*)d_in[9];
    const float* g1b  =(const float*)d_in[10];
    const float* c2w  =(const float*)d_in[11];
    const float* c2b  =(const float*)d_in[12];
    const float* g2s  =(const float*)d_in[13];
    const float* g2b  =(const float*)d_in[14];
    const float* gw1  =(const float*)d_in[15];
    const float* gb1  =(const float*)d_in[16];
    const float* gw2  =(const float*)d_in[17];
    const float* gb2  =(const float*)d_in[18];
    const float* rpw  =(const float*)d_in[19];
    const float* rpb  =(const float*)d_in[20];
    const float* rs   =(const float*)d_in[21];
    const float* cfw  =(const float*)d_in[22];
    const float* cfb  =(const float*)d_in[23];
    const float* mixs =(const float*)d_in[24];
    float* dout=(float*)d_out;

    static int smem_set=0;
    if(!smem_set){
        cudaFuncSetAttribute(k_mconv<97,112,7,0>,
            cudaFuncAttributeMaxDynamicSharedMemorySize, SM_BYTES);
        cudaFuncSetAttribute(k_mconv<96,96,6,1>,
            cudaFuncAttributeMaxDynamicSharedMemorySize, SM_BYTES);
        smem_set=1;
    }

    k_zero<<<512,256>>>();                                          // 0
    k_prep<<<1024,256>>>(uvs,msk,wg,wb,wh);                         // 1
    k_scatter<<<dim3(64,16),256>>>(vf);                             // 2
    k_finalize<<<512,256>>>();                                      // 3
    k_wtrans<0,7><<<(NG1*192*BROW+255)/256,256>>>(c1w);             // 4
    k_wtrans<1,6><<<(NG2*192*BROW+255)/256,256>>>(c2w);             // 5
    k_uncert<<<512,256>>>(dout);                                    // 6
    k_mconv<97,112,7,0><<<dim3(512,2,Bn),256,SM_BYTES>>>(c1b);      // 7
    k_chansum<0><<<Bn*COn,256>>>();                                 // 8
    k_stats<<<1,384>>>(g1s,g1b);                                    // 9
    k_apply1<<<dim3(256,96,2),256>>>();                             // 10
    k_mconv<96,96,6,1><<<dim3(512,2,Bn),256,SM_BYTES>>>(c2b);       // 11
    k_chansum<1><<<Bn*COn,256>>>();                                 // 12
    k_stats<<<1,384>>>(g2s,g2b);                                    // 13
    k_poolsum<<<Bn*COn,256>>>();                                    // 14
    k_gate<<<1,192>>>(gw1,gb1,gw2,gb2);                             // 15
    k_res_combine<<<dim3(256,3,2),256>>>(rpw,rpb,rs,mixs,cfw,cfb,dout); // 16
}

// round 16
// speedup vs baseline: 1.0342x; 1.0250x over previous
#include <cuda_runtime.h>
#include <cuda_fp16.h>
#include <math.h>
#include <stdint.h>

typedef unsigned long long ull;

constexpr int Bn=2, Vn=8, Cn=64, An=256;
constexpr int HWn=128*128, Pn=An*An;
constexpr int C3n=194, COn=192, HIDn=48;

constexpr size_t CTXN=(size_t)Bn*C3n*Pn;
constexpr size_t CNTN=(size_t)Bn*3*Pn;
constexpr size_t OFF_COV =(size_t)3*Bn*Cn*Pn;
constexpr size_t OFF_UNC =OFF_COV+(size_t)Bn*Pn;
constexpr size_t OFF_CONF=OFF_UNC+(size_t)Bn*Pn;

constexpr int NG1=21;
constexpr int NG2=18;
constexpr int BROW=104;

__device__ float  g_ctx[CTXN];
__device__ float  g_cnt[CNTN];
__device__ float  g_uraw[(size_t)Bn*Pn];
__device__ int    g_umax[Bn];
__device__ int    g_idx[Bn*Vn*HWn];
__device__ float  g_wts[3][Bn*Vn*HWn];
__device__ float  g_h1[(size_t)Bn*COn*Pn];   // conv1 raw out, fp16 pair-packed (uses half)
__device__ float  g_h2[(size_t)Bn*COn*Pn];
__device__ uint32_t g_ctxh[(size_t)Bn*112*Pn];
__device__ uint32_t g_h1h [(size_t)Bn*96*Pn];
__device__ unsigned short g_wTc1h[NG1*192*BROW];
__device__ unsigned short g_wTc2h[NG2*192*BROW];
__device__ float  g_csum[Bn*COn*2];
__device__ float  g_sA[Bn*COn], g_sB[Bn*COn];
__device__ float  g_gate[Bn*COn];
__device__ float  g_pool[Bn*COn];

__device__ __forceinline__ float siluf(float x){ return x/(1.f+__expf(-x)); }
__device__ __forceinline__ float sigf(float x){ return 1.f/(1.f+__expf(-x)); }
__device__ __forceinline__ uint32_t smem_u32(const void* p){
    uint32_t a;
    asm("{ .reg .u64 t; cvta.to.shared.u64 t, %1; cvt.u32.u64 %0, t; }":"=r"(a):"l"(p));
    return a;
}
__device__ __forceinline__ void ldmx4(uint32_t* r, uint32_t addr){
    asm volatile("ldmatrix.sync.aligned.m8n8.x4.shared.b16 {%0,%1,%2,%3},[%4];"
        :"=r"(r[0]),"=r"(r[1]),"=r"(r[2]),"=r"(r[3]):"r"(addr));
}
__device__ __forceinline__ void mma_f16(float* c, const uint32_t* a, const uint32_t* b){
    asm volatile("mma.sync.aligned.m16n8k16.row.col.f32.f16.f16.f32 "
        "{%0,%1,%2,%3},{%4,%5,%6,%7},{%8,%9},{%0,%1,%2,%3};"
        :"+f"(c[0]),"+f"(c[1]),"+f"(c[2]),"+f"(c[3])
        :"r"(a[0]),"r"(a[1]),"r"(a[2]),"r"(a[3]),"r"(b[0]),"r"(b[1]));
}
__device__ __forceinline__ uint32_t packh2(float lo, float hi){
    __half2 h=__floats2half2_rn(lo,hi);
    return *reinterpret_cast<uint32_t*>(&h);
}

__global__ void k_zero(){
    size_t st=(size_t)gridDim.x*blockDim.x;
    for(size_t i=(size_t)blockIdx.x*blockDim.x+threadIdx.x; i<CTXN+CNTN; i+=st){
        if(i<CTXN) g_ctx[i]=0.f; else g_cnt[i-CTXN]=0.f;
    }
    if(blockIdx.x==0){
        if(threadIdx.x<Bn) g_umax[threadIdx.x]=0;
        for(int t=threadIdx.x;t<Bn*COn*2;t+=blockDim.x) g_csum[t]=0.f;
    }
}

__global__ void k_prep(const float* __restrict__ uvs, const float* __restrict__ msk,
                       const float* __restrict__ wg, const float* __restrict__ wb,
                       const float* __restrict__ wh){
    int i=blockIdx.x*blockDim.x+threadIdx.x;
    if(i>=Bn*Vn*HWn) return;
    float u=uvs[2*i], v=uvs[2*i+1];
    bool fin=isfinite(u)&&isfinite(v);
    float su=fin?u:0.f, sv=fin?v:0.f;
    int xi=(int)rintf(fminf(fmaxf(su,0.f),1.f)*(float)(An-1));
    int yi=(int)rintf((1.f-fminf(fmaxf(sv,0.f),1.f))*(float)(An-1));
    g_idx[i]=yi*An+xi;
    bool mv=(msk[i]>0.5f)&&fin;
    int bv=i/HWn;
    float w0=fmaxf(wg[bv],0.f), w1=fmaxf(wb[bv],0.f), w2=fmaxf(wh[bv],0.f);
    g_wts[0][i]=(mv&&w0>0.f)?w0:0.f;
    g_wts[1][i]=(mv&&w1>0.f)?w1:0.f;
    g_wts[2][i]=(mv&&w2>0.f)?w2:0.f;
}

__global__ void k_scatter(const float* __restrict__ vf){
    int bv=blockIdx.y;
    int px=blockIdx.x*blockDim.x+threadIdx.x;
    int i=bv*HWn+px;
    int b=bv>>3;
    int idx=g_idx[i];
    float w0=g_wts[0][i], w1=g_wts[1][i], w2=g_wts[2][i];
    if(w0<=0.f && w1<=0.f && w2<=0.f) return;
    float* base=g_ctx+(size_t)b*C3n*Pn+idx;
    const float* vp=vf+(size_t)bv*Cn*HWn+px;
    #pragma unroll 4
    for(int c=0;c<Cn;c++){
        float v=vp[(size_t)c*HWn];
        if(w0>0.f) atomicAdd(base+(size_t)c*Pn, w0*v);
        if(w1>0.f) atomicAdd(base+(size_t)(Cn+c)*Pn, w1*v);
        if(w2>0.f) atomicAdd(base+(size_t)(2*Cn+c)*Pn, w2*v);
    }
    if(w0>0.f) atomicAdd(&g_cnt[((size_t)b*3+0)*Pn+idx], w0);
    if(w1>0.f) atomicAdd(&g_cnt[((size_t)b*3+1)*Pn+idx], w1);
    if(w2>0.f) atomicAdd(&g_cnt[((size_t)b*3+2)*Pn+idx], w2);
}

__global__ void k_finalize(){
    int i=blockIdx.x*blockDim.x+threadIdx.x;
    int b=i>>16, px=i&(Pn-1);
    size_t base=(size_t)b*C3n*Pn+px;
    size_t hbase=(size_t)b*112*Pn+px;
    float c0=g_cnt[((size_t)b*3+0)*Pn+px];
    float c1=g_cnt[((size_t)b*3+1)*Pn+px];
    float c2=g_cnt[((size_t)b*3+2)*Pn+px];
    float i0=1.f/fmaxf(c0,1.f), i1=1.f/fmaxf(c1,1.f), i2=1.f/fmaxf(c2,1.f);
    float ss=0.f;
    #pragma unroll 4
    for(int c2i=0;c2i<32;c2i++){
        int c=2*c2i;
        float ga=g_ctx[base+(size_t)c*Pn]*i0;
        float gb=g_ctx[base+(size_t)(c+1)*Pn]*i0;
        float ha=g_ctx[base+(size_t)(Cn+c)*Pn]*i1;
        float hb=g_ctx[base+(size_t)(Cn+c+1)*Pn]*i1;
        float ta=g_ctx[base+(size_t)(2*Cn+c)*Pn]*i2;
        float tb=g_ctx[base+(size_t)(2*Cn+c+1)*Pn]*i2;
        g_ctx[base+(size_t)c*Pn]=ga;
        g_ctx[base+(size_t)(c+1)*Pn]=gb;
        g_ctx[base+(size_t)(Cn+c)*Pn]=ha;
        g_ctx[base+(size_t)(Cn+c+1)*Pn]=hb;
        g_ctx[base+(size_t)(2*Cn+c)*Pn]=ta;
        g_ctx[base+(size_t)(2*Cn+c+1)*Pn]=tb;
        g_ctxh[hbase+(size_t)c2i*Pn]      =packh2(ga,gb);
        g_ctxh[hbase+(size_t)(32+c2i)*Pn] =packh2(ha,hb);
        g_ctxh[hbase+(size_t)(64+c2i)*Pn] =packh2(ta,tb);
        float ma=(ga+ha+ta)*(1.f/3.f);
        float mb=(gb+hb+tb)*(1.f/3.f);
        float d0=ga-ma,d1=ha-ma,d2=ta-ma,d3=gb-mb,d4=hb-mb,d5=tb-mb;
        ss+=d0*d0+d1*d1+d2*d2+d3*d3+d4*d4+d5*d5;
    }
    float cov=((c0>0.f?1.f:0.f)+(c1>0.f?1.f:0.f)+(c2>0.f?1.f:0.f))*(1.f/3.f);
    cov=fminf(cov,1.f);
    float uraw=sqrtf(ss*(1.f/(3.f*Cn)));
    g_ctx[base+(size_t)192*Pn]=cov;
    g_uraw[i]=uraw;
    float m=uraw;
    #pragma unroll
    for(int o=16;o>0;o>>=1) m=fmaxf(m,__shfl_xor_sync(0xffffffffu,m,o));
    if((threadIdx.x&31)==0) atomicMax(&g_umax[b], __float_as_int(m));
}

__global__ void k_uncert(float* __restrict__ dout){
    int i=blockIdx.x*blockDim.x+threadIdx.x;
    int b=i>>16, px=i&(Pn-1);
    size_t base=(size_t)b*C3n*Pn+px;
    float cov=g_ctx[base+(size_t)192*Pn];
    float sc=fmaxf(__int_as_float(g_umax[b]),1e-6f);
    float un=fminf(fmaxf(g_uraw[i]/sc,0.f),1.f)*cov;
    g_ctx[base+(size_t)193*Pn]=un;
    g_ctxh[((size_t)b*112+96)*Pn+px]=packh2(cov,un);
    dout[OFF_COV+i]=cov;
    dout[OFF_UNC+i]=un;
}

template<int MODE,int CIB>
__global__ void k_wtrans(const float* __restrict__ w){
    constexpr int CIN =(MODE==0)?C3n:COn;
    constexpr int NG  =3*CIB;
    int n=NG*192*BROW;
    int i=blockIdx.x*blockDim.x+threadIdx.x;
    if(i>=n) return;
    int grp=i/(192*BROW);
    int r=i-grp*(192*BROW);
    int co=r/BROW, k=r-co*BROW;
    float v=0.f;
    if(k<96){
        int dy=grp/CIB, cib=grp-dy*CIB;
        int dx=k>>5, ci=cib*32+(k&31);
        int tap=dy*3+dx;
        v=(ci<CIN)?w[((size_t)co*CIN+ci)*9+tap]:0.f;
    }
    unsigned short hv=__half_as_ushort(__float2half_rn(v));
    if(MODE==0) g_wTc1h[i]=hv; else g_wTc2h[i]=hv;
}

constexpr int SMA=9728;
constexpr int SMBb=19968;
constexpr int SMB0b=2*SMA;
constexpr int SM_BYTES=SMB0b+2*SMBb;

template<int CI2,int CI2P,int CIB,int MODE>
__global__ void __launch_bounds__(256,2) k_mconv(const float* __restrict__ bias){
    constexpr int NG=3*CIB;
    extern __shared__ __align__(1024) char smem[];
    const uint32_t* inH=(MODE==0)?g_ctxh:g_h1h;
    const unsigned short* wT=(MODE==0)?g_wTc1h:g_wTc2h;
    const int tid=threadIdx.x, wid=tid>>5, lane=tid&31;
    const int sb=blockIdx.x, cn=blockIdx.y, b=blockIdx.z;
    const int y=sb>>1, x0=(sb&1)*128;
    const uint32_t* inB=inH+(size_t)b*CI2P*Pn;
    const uint32_t sbase=smem_u32(smem);
    const uint32_t* Aw=(const uint32_t*)smem;

    const int wm=wid&3, wn=wid>>2;
    const int g=lane>>2, tig=lane&3;
    const int nrow=(lane&7)+((lane>>4)<<3);
    const uint32_t blane=(uint32_t)(nrow*208+((lane&8)?16:0));

    float acc[2][6][4];
    #pragma unroll
    for(int mt=0;mt<2;mt++)
        #pragma unroll
        for(int nt=0;nt<6;nt++)
            #pragma unroll
            for(int q=0;q<4;q++) acc[mt][nt][q]=0.f;

    auto prefA=[&](int grp,int buf){
        int dy=grp/CIB, cib=grp-dy*CIB;
        int gy=y+dy-1;
        bool rok=((unsigned)gy<256u);
        uint32_t ab=sbase+(uint32_t)buf*SMA;
        #pragma unroll 1
        for(int l=tid;l<576;l+=256){
            int ci=l/36, v=l-ci*36;
            int ci2g=cib*16+ci;
            int px0=x0-8+4*v;
            bool ok=rok&&(ci2g<CI2)&&((unsigned)px0<253u);
            const uint32_t* src=inB+(size_t)(ok?ci2g:0)*Pn+(ok?(gy*256+px0):0);
            unsigned sz=ok?16u:0u;
            asm volatile("cp.async.cg.shared.global [%0],[%1],16,%2;"
                ::"r"(ab+(uint32_t)(ci*152+4*v)*4u),"l"(src),"r"(sz));
        }
    };
    auto prefB=[&](int grp,int buf){
        const float4* ws=(const float4*)(wT+(size_t)grp*(192*BROW)+(size_t)cn*(96*BROW));
        uint32_t bd=sbase+SMB0b+(uint32_t)buf*SMBb;
        #pragma unroll 1
        for(int l=tid;l<1248;l+=256)
            asm volatile("cp.async.cg.shared.global [%0],[%1],16;"
                ::"r"(bd+(uint32_t)l*16u),"l"(ws+l));
    };

    prefA(0,0); prefB(0,0);
    asm volatile("cp.async.commit_group;");

    #pragma unroll 1
    for(int grp=0;grp<NG;grp++){
        asm volatile("cp.async.wait_group 0;");
        __syncthreads();
        if(grp+1<NG){
            prefA(grp+1,(grp+1)&1);
            prefB(grp+1,(grp+1)&1);
            asm volatile("cp.async.commit_group;");
        }
        const int buf=grp&1;
        const uint32_t* As=Aw+buf*(SMA/4);
        const uint32_t bbase=sbase+SMB0b+(uint32_t)buf*SMBb+blane;
        #pragma unroll
        for(int kk=0;kk<6;kk++){
            const int dx=kk>>1;
            uint32_t bf[3][4];
            #pragma unroll
            for(int p=0;p<3;p++)
                ldmx4(bf[p], bbase+(uint32_t)((wn*48+p*16)*208)+(uint32_t)(kk*32));
            const int arow=((kk&1)*8+tig)*152;
            const int pxo=dx+7+g;
            #pragma unroll
            for(int mt=0;mt<2;mt++){
                uint32_t af[4];
                int ab=arow+wm*32+mt*16+pxo;
                af[0]=As[ab];
                af[1]=As[ab+8];
                af[2]=As[ab+4*152];
                af[3]=As[ab+4*152+8];
                #pragma unroll
                for(int nt=0;nt<6;nt++)
                    mma_f16(acc[mt][nt], af, &bf[nt>>1][(nt&1)*2]);
            }
        }
    }

    // epilogue: bias + stores + fused per-channel sum/sumsq
    const int row0=wm*32+(lane>>2);
    const int col0=cn*96+wn*48+2*(lane&3);
    const size_t pxb=(size_t)y*256+x0;
    float sa[6][2], qa[6][2];
    #pragma unroll
    for(int nt=0;nt<6;nt++){ sa[nt][0]=0;sa[nt][1]=0;qa[nt][0]=0;qa[nt][1]=0; }

    #pragma unroll
    for(int mt=0;mt<2;mt++){
        int r0=row0+mt*16;
        #pragma unroll
        for(int nt=0;nt<6;nt++){
            int co=col0+nt*8;
            float b0=__ldg(bias+co), b1=__ldg(bias+co+1);
            float v0=acc[mt][nt][0]+b0, v1=acc[mt][nt][1]+b1;
            float v2=acc[mt][nt][2]+b0, v3=acc[mt][nt][3]+b1;
            if(MODE==0){
                uint32_t* op=reinterpret_cast<uint32_t*>(g_h1)
                    +((size_t)(b*96+(co>>1)))*Pn+pxb;
                op[r0]  =packh2(v0,v1);
                op[r0+8]=packh2(v2,v3);
            }else{
                float* o0=g_h2+(size_t)(b*COn+co)*Pn+pxb;
                float* o1=o0+Pn;
                o0[r0]=v0; o1[r0]=v1; o0[r0+8]=v2; o1[r0+8]=v3;
            }
            sa[nt][0]+=v0+v2; qa[nt][0]+=v0*v0+v2*v2;
            sa[nt][1]+=v1+v3; qa[nt][1]+=v1*v1+v3*v3;
        }
    }
    #pragma unroll
    for(int nt=0;nt<6;nt++)
        #pragma unroll
        for(int h=0;h<2;h++){
            float s=sa[nt][h], q=qa[nt][h];
            #pragma unroll
            for(int o=4;o<32;o<<=1){
                s+=__shfl_xor_sync(0xffffffffu,s,o);
                q+=__shfl_xor_sync(0xffffffffu,q,o);
            }
            if(lane<4){
                int co=col0+nt*8+h;
                atomicAdd(&g_csum[(b*COn+co)*2],s);
                atomicAdd(&g_csum[(b*COn+co)*2+1],q);
            }
        }
}

// group stats -> per-channel affine; re-zero g_csum for next accumulation
__global__ void k_stats(const float* __restrict__ scale, const float* __restrict__ shift){
    __shared__ float gm[16], gr[16];
    int t=threadIdx.x;
    if(t<Bn*8){
        int b=t/8, g=t%8;
        float s=0.f,q=0.f;
        for(int c=0;c<24;c++){
            s+=g_csum[(b*COn+g*24+c)*2];
            q+=g_csum[(b*COn+g*24+c)*2+1];
        }
        float N=24.f*(float)Pn;
        float mean=s/N;
        float var=q/N-mean*mean;
        gm[t]=mean;
        gr[t]=rsqrtf(var+1e-5f);
    }
    __syncthreads();
    if(t<Bn*COn){
        int b=t/COn, c=t%COn, g=c/24;
        float a=gr[b*8+g]*scale[c];
        g_sA[t]=a;
        g_sB[t]=shift[c]-gm[b*8+g]*a;
        g_csum[t*2]=0.f; g_csum[t*2+1]=0.f;
    }
}

// GN1 + SiLU from fp16 raw pairs -> fp16 packed h1h
__global__ void k_apply1(){
    int px=blockIdx.x*blockDim.x+threadIdx.x;
    int c2=blockIdx.y, b=blockIdx.z;
    int bc=b*COn+2*c2;
    uint32_t w=reinterpret_cast<const uint32_t*>(g_h1)[((size_t)(b*96+c2))*Pn+px];
    __half2 hh=*reinterpret_cast<__half2*>(&w);
    float v0=siluf(__low2float(hh)*g_sA[bc]+g_sB[bc]);
    float v1=siluf(__high2float(hh)*g_sA[bc+1]+g_sB[bc+1]);
    g_h1h[((size_t)b*96+c2)*Pn+px]=packh2(v0,v1);
}

__global__ void k_poolsum(){
    __shared__ float red[256];
    int bc=blockIdx.x;
    const float* p=g_h2+(size_t)bc*Pn;
    float a=g_sA[bc], s0=g_sB[bc];
    float s=0.f;
    for(int i=threadIdx.x;i<Pn;i+=256) s+=siluf(p[i]*a+s0);
    red[threadIdx.x]=s;
    __syncthreads();
    for(int st=128;st>0;st>>=1){
        if(threadIdx.x<st) red[threadIdx.x]+=red[threadIdx.x+st];
        __syncthreads();
    }
    if(threadIdx.x==0) g_pool[bc]=red[0];
}

__global__ void k_gate(const float* __restrict__ gw1, const float* __restrict__ gb1,
                       const float* __restrict__ gw2, const float* __restrict__ gb2){
    __shared__ float pooled[COn];
    __shared__ float hbuf[HIDn];
    for(int b=0;b<Bn;b++){
        for(int c=threadIdx.x;c<COn;c+=blockDim.x)
            pooled[c]=g_pool[b*COn+c]*(1.f/(float)Pn);
        __syncthreads();
        if(threadIdx.x<HIDn){
            float s=gb1[threadIdx.x];
            for(int c=0;c<COn;c++) s+=gw1[threadIdx.x*COn+c]*pooled[c];
            hbuf[threadIdx.x]=siluf(s);
        }
        __syncthreads();
        if(threadIdx.x<COn){
            float s=gb2[threadIdx.x];
            for(int j=0;j<HIDn;j++) s+=gw2[threadIdx.x*HIDn+j]*hbuf[j];
            g_gate[b*COn+threadIdx.x]=0.5f+sigf(s);
        }
        __syncthreads();
    }
}

__device__ __forceinline__ ull pack2(float v){ ull r; asm("mov.b64 %0,{%1,%1};":"=l"(r):"f"(v)); return r; }
__device__ __forceinline__ void fma2(ull&a, ull x, ull w){ asm("fma.rn.f32x2 %0,%1,%2,%0;":"+l"(a):"l"(x),"l"(w)); }
__device__ __forceinline__ void unpack2(ull v, float&lo, float&hi){ asm("mov.b64 {%0,%1},%2;":"=f"(lo),"=f"(hi):"l"(v)); }

// residual 1x1 (fp16 ctx reads) + conf + GN2/SiLU + gate + mix -> outputs
__global__ void __launch_bounds__(256) k_res_combine(
    const float* __restrict__ rpw, const float* __restrict__ rpb,
    const float* __restrict__ prs, const float* __restrict__ pmix,
    const float* __restrict__ cfw, const float* __restrict__ cfb,
    float* __restrict__ dout){
    __shared__ __align__(16) float s_w[98*64];
    __shared__ float s_cwb[98];
    __shared__ float s_sA[64], s_sB[64], s_g[64];
    const int br=blockIdx.y, b=blockIdx.z;
    const int og=threadIdx.x>>6, pl=threadIdx.x&63;
    const int pxb=blockIdx.x*256;
    const float* ctxb=g_ctx+(size_t)b*C3n*Pn;
    const uint32_t* ctxhb=g_ctxh+(size_t)b*112*Pn;

    if(threadIdx.x<64){
        int bc=b*COn+br*64+threadIdx.x;
        s_sA[threadIdx.x]=g_sA[bc];
        s_sB[threadIdx.x]=g_sB[bc];
        s_g[threadIdx.x]=g_gate[bc];
    }

    ull acc[4][8];
    #pragma unroll
    for(int k=0;k<4;k++)
        #pragma unroll
        for(int j=0;j<8;j++) acc[k][j]=0;
    float cf[4]={0.f,0.f,0.f,0.f};

    #pragma unroll 1
    for(int half=0;half<2;half++){
        const int ci0=half?96:0;
        const int nci=half?98:96;
        const int p0=half?48:0;
        for(int l=threadIdx.x;l<nci*64;l+=256){
            int ci=l>>6, o=l&63;
            s_w[l]=rpw[(size_t)(br*64+o)*C3n+ci0+ci];
        }
        if(threadIdx.x<nci) s_cwb[threadIdx.x]=cfw[br*C3n+ci0+threadIdx.x];
        __syncthreads();
        #pragma unroll 1
        for(int p=0;p<(half?49:48);p++){
            const uint32_t* xp=ctxhb+(size_t)(p0+p)*Pn+pxb+pl;
            uint32_t w0=xp[0], w1=xp[64], w2=xp[128], w3=xp[192];
            __half2 h0=*reinterpret_cast<__half2*>(&w0);
            __half2 h1=*reinterpret_cast<__half2*>(&w1);
            __half2 h2=*reinterpret_cast<__half2*>(&w2);
            __half2 h3=*reinterpret_cast<__half2*>(&w3);
            float xa0=__low2float(h0), xb0=__high2float(h0);
            float xa1=__low2float(h1), xb1=__high2float(h1);
            float xa2=__low2float(h2), xb2=__high2float(h2);
            float xa3=__low2float(h3), xb3=__high2float(h3);
            float cwa=s_cwb[2*p], cwb=s_cwb[2*p+1];
            cf[0]+=xa0*cwa+xb0*cwb;
            cf[1]+=xa1*cwa+xb1*cwb;
            cf[2]+=xa2*cwa+xb2*cwb;
            cf[3]+=xa3*cwa+xb3*cwb;
            ull pa0=pack2(xa0), pa1=pack2(xa1), pa2=pack2(xa2), pa3=pack2(xa3);
            ull pb0=pack2(xb0), pb1=pack2(xb1), pb2=pack2(xb2), pb3=pack2(xb3);
            const ull* wra=reinterpret_cast<const ull*>(s_w+(2*p)*64+og*16);
            const ull* wrb=reinterpret_cast<const ull*>(s_w+(2*p+1)*64+og*16);
            #pragma unroll
            for(int j=0;j<8;j++){
                ull wa=wra[j];
                fma2(acc[0][j],pa0,wa); fma2(acc[1][j],pa1,wa);
                fma2(acc[2][j],pa2,wa); fma2(acc[3][j],pa3,wa);
            }
            #pragma unroll
            for(int j=0;j<8;j++){
                ull wb=wrb[j];
                fma2(acc[0][j],pb0,wb); fma2(acc[1][j],pb1,wb);
                fma2(acc[2][j],pb2,wb); fma2(acc[3][j],pb3,wb);
            }
        }
        __syncthreads();
    }

    const float trs=tanhf(prs[0]);
    const float ms=tanhf(pmix[0]);
    const float cb=cfb[br];
    #pragma unroll
    for(int k=0;k<4;k++){
        int px=pxb+pl+k*64;
        float confv=sigf(cf[k]+cb);
        dout[OFF_CONF+((size_t)(b*3+br))*Pn+px]=confv;
        #pragma unroll
        for(int j=0;j<8;j++){
            float lo,hi; unpack2(acc[k][j],lo,hi);
            #pragma unroll
            for(int half=0;half<2;half++){
                int c=og*16+2*j+half;
                int co=br*64+c;
                float res=(half?hi:lo)+rpb[co];
                float hraw=g_h2[((size_t)(b*COn)+co)*Pn+px];
                float h=siluf(hraw*s_sA[c]+s_sB[c]);
                float refine=h*s_g[c]+trs*res;
                float feat=ctxb[(size_t)co*Pn+px];
                dout[(size_t)br*((size_t)Bn*Cn*Pn)+((size_t)(b*Cn+c))*Pn+px]
                    =feat+ms*refine*confv;
            }
        }
    }
}

extern "C" void kernel_launch(void* const* d_in, const int* in_sizes, int n_in,
                              void* d_out, int out_size){
    const float* vf   =(const float*)d_in[0];
    const float* uvs  =(const float*)d_in[1];
    const float* msk  =(const float*)d_in[2];
    const float* wg   =(const float*)d_in[3];
    const float* wb   =(const float*)d_in[4];
    const float* wh   =(const float*)d_in[5];
    const float* c1w  =(const float*)d_in[7];
    const float* c1b  =(const float*)d_in[8];
    const float* g1s  =(const float*)d_in[9];
    const float* g1b  =(const float*)d_in[10];
    const float* c2w  =(const float*)d_in[11];
    const float* c2b  =(const float*)d_in[12];
    const float* g2s  =(const float*)d_in[13];
    const float* g2b  =(const float*)d_in[14];
    const float* gw1  =(const float*)d_in[15];
    const float* gb1  =(const float*)d_in[16];
    const float* gw2  =(const float*)d_in[17];
    const float* gb2  =(const float*)d_in[18];
    const float* rpw  =(const float*)d_in[19];
    const float* rpb  =(const float*)d_in[20];
    const float* rs   =(const float*)d_in[21];
    const float* cfw  =(const float*)d_in[22];
    const float* cfb  =(const float*)d_in[23];
    const float* mixs =(const float*)d_in[24];
    float* dout=(float*)d_out;

    static int smem_set=0;
    if(!smem_set){
        cudaFuncSetAttribute(k_mconv<97,112,7,0>,
            cudaFuncAttributeMaxDynamicSharedMemorySize, SM_BYTES);
        cudaFuncSetAttribute(k_mconv<96,96,6,1>,
            cudaFuncAttributeMaxDynamicSharedMemorySize, SM_BYTES);
        smem_set=1;
    }

    k_zero<<<512,256>>>();                                          // 0
    k_prep<<<1024,256>>>(uvs,msk,wg,wb,wh);                         // 1
    k_scatter<<<dim3(64,16),256>>>(vf);                             // 2
    k_finalize<<<512,256>>>();                                      // 3
    k_wtrans<0,7><<<(NG1*192*BROW+255)/256,256>>>(c1w);             // 4
    k_wtrans<1,6><<<(NG2*192*BROW+255)/256,256>>>(c2w);             // 5
    k_uncert<<<512,256>>>(dout);                                    // 6
    k_mconv<97,112,7,0><<<dim3(512,2,Bn),256,SM_BYTES>>>(c1b);      // 7
    k_stats<<<1,384>>>(g1s,g1b);                                    // 8
    k_apply1<<<dim3(256,96,2),256>>>();                             // 9
    k_mconv<96,96,6,1><<<dim3(512,2,Bn),256,SM_BYTES>>>(c2b);       // 10
    k_stats<<<1,384>>>(g2s,g2b);                                    // 11
    k_poolsum<<<Bn*COn,256>>>();                                    // 12
    k_gate<<<1,192>>>(gw1,gb1,gw2,gb2);                             // 13
    k_res_combine<<<dim3(256,3,2),256>>>(rpw,rpb,rs,mixs,cfw,cfb,dout); // 14
}

// round 17
// speedup vs baseline: 1.1738x; 1.1350x over previous
#include <cuda_runtime.h>
#include <cuda_fp16.h>
#include <math.h>
#include <stdint.h>

typedef unsigned long long ull;

constexpr int Bn=2, Vn=8, Cn=64, An=256;
constexpr int HWn=128*128, Pn=An*An;
constexpr int C3n=194, COn=192, HIDn=48;

constexpr size_t CTXN=(size_t)Bn*C3n*Pn;
constexpr size_t CNTN=(size_t)Bn*3*Pn;
constexpr size_t OFF_COV =(size_t)3*Bn*Cn*Pn;
constexpr size_t OFF_UNC =OFF_COV+(size_t)Bn*Pn;
constexpr size_t OFF_CONF=OFF_UNC+(size_t)Bn*Pn;

constexpr int NG1=21;
constexpr int NG2=18;
constexpr int BROW=104;

__device__ float  g_ctx[CTXN];
__device__ float  g_cnt[CNTN];
__device__ float  g_uraw[(size_t)Bn*Pn];
__device__ int    g_umax[Bn];
__device__ uint32_t g_h1r[(size_t)Bn*96*Pn];   // conv1 raw out, fp16 pair-packed
__device__ uint32_t g_h2r[(size_t)Bn*96*Pn];   // conv2 raw out, fp16 pair-packed
__device__ uint32_t g_ctxh[(size_t)Bn*112*Pn];
__device__ uint32_t g_h1h [(size_t)Bn*96*Pn];
__device__ unsigned short g_wTc1h[NG1*192*BROW];
__device__ unsigned short g_wTc2h[NG2*192*BROW];
__device__ float  g_csum[Bn*COn*2];
__device__ float  g_sA[Bn*COn], g_sB[Bn*COn];
__device__ float  g_gate[Bn*COn];
__device__ float  g_pool[Bn*COn];

__device__ __forceinline__ float siluf(float x){ return x/(1.f+__expf(-x)); }
__device__ __forceinline__ float sigf(float x){ return 1.f/(1.f+__expf(-x)); }
__device__ __forceinline__ uint32_t smem_u32(const void* p){
    uint32_t a;
    asm("{ .reg .u64 t; cvta.to.shared.u64 t, %1; cvt.u32.u64 %0, t; }":"=r"(a):"l"(p));
    return a;
}
__device__ __forceinline__ void ldmx4(uint32_t* r, uint32_t addr){
    asm volatile("ldmatrix.sync.aligned.m8n8.x4.shared.b16 {%0,%1,%2,%3},[%4];"
        :"=r"(r[0]),"=r"(r[1]),"=r"(r[2]),"=r"(r[3]):"r"(addr));
}
__device__ __forceinline__ void mma_f16(float* c, const uint32_t* a, const uint32_t* b){
    asm volatile("mma.sync.aligned.m16n8k16.row.col.f32.f16.f16.f32 "
        "{%0,%1,%2,%3},{%4,%5,%6,%7},{%8,%9},{%0,%1,%2,%3};"
        :"+f"(c[0]),"+f"(c[1]),"+f"(c[2]),"+f"(c[3])
        :"r"(a[0]),"r"(a[1]),"r"(a[2]),"r"(a[3]),"r"(b[0]),"r"(b[1]));
}
__device__ __forceinline__ uint32_t packh2(float lo, float hi){
    __half2 h=__floats2half2_rn(lo,hi);
    return *reinterpret_cast<uint32_t*>(&h);
}

__global__ void k_zero(){
    size_t st=(size_t)gridDim.x*blockDim.x;
    for(size_t i=(size_t)blockIdx.x*blockDim.x+threadIdx.x; i<CTXN+CNTN; i+=st){
        if(i<CTXN) g_ctx[i]=0.f; else g_cnt[i-CTXN]=0.f;
    }
    if(blockIdx.x==0){
        if(threadIdx.x<Bn) g_umax[threadIdx.x]=0;
        for(int t=threadIdx.x;t<Bn*COn*2;t+=blockDim.x) g_csum[t]=0.f;
    }
}

// fused uv-prep + scatter-add
__global__ void k_scatter(const float* __restrict__ vf, const float* __restrict__ uvs,
                          const float* __restrict__ msk,
                          const float* __restrict__ wg, const float* __restrict__ wb,
                          const float* __restrict__ wh){
    int bv=blockIdx.y;
    int px=blockIdx.x*blockDim.x+threadIdx.x;
    int i=bv*HWn+px;
    int b=bv>>3;
    float u=uvs[2*i], v=uvs[2*i+1];
    bool fin=isfinite(u)&&isfinite(v);
    float su=fin?u:0.f, sv=fin?v:0.f;
    int xi=(int)rintf(fminf(fmaxf(su,0.f),1.f)*(float)(An-1));
    int yi=(int)rintf((1.f-fminf(fmaxf(sv,0.f),1.f))*(float)(An-1));
    int idx=yi*An+xi;
    bool mv=(msk[i]>0.5f)&&fin;
    float w0=fmaxf(wg[bv],0.f), w1=fmaxf(wb[bv],0.f), w2=fmaxf(wh[bv],0.f);
    w0=(mv&&w0>0.f)?w0:0.f;
    w1=(mv&&w1>0.f)?w1:0.f;
    w2=(mv&&w2>0.f)?w2:0.f;
    if(w0<=0.f && w1<=0.f && w2<=0.f) return;
    float* base=g_ctx+(size_t)b*C3n*Pn+idx;
    const float* vp=vf+(size_t)bv*Cn*HWn+px;
    #pragma unroll 4
    for(int c=0;c<Cn;c++){
        float x=vp[(size_t)c*HWn];
        if(w0>0.f) atomicAdd(base+(size_t)c*Pn, w0*x);
        if(w1>0.f) atomicAdd(base+(size_t)(Cn+c)*Pn, w1*x);
        if(w2>0.f) atomicAdd(base+(size_t)(2*Cn+c)*Pn, w2*x);
    }
    if(w0>0.f) atomicAdd(&g_cnt[((size_t)b*3+0)*Pn+idx], w0);
    if(w1>0.f) atomicAdd(&g_cnt[((size_t)b*3+1)*Pn+idx], w1);
    if(w2>0.f) atomicAdd(&g_cnt[((size_t)b*3+2)*Pn+idx], w2);
}

__global__ void k_finalize(){
    int i=blockIdx.x*blockDim.x+threadIdx.x;
    int b=i>>16, px=i&(Pn-1);
    size_t base=(size_t)b*C3n*Pn+px;
    size_t hbase=(size_t)b*112*Pn+px;
    float c0=g_cnt[((size_t)b*3+0)*Pn+px];
    float c1=g_cnt[((size_t)b*3+1)*Pn+px];
    float c2=g_cnt[((size_t)b*3+2)*Pn+px];
    float i0=1.f/fmaxf(c0,1.f), i1=1.f/fmaxf(c1,1.f), i2=1.f/fmaxf(c2,1.f);
    float ss=0.f;
    #pragma unroll 4
    for(int c2i=0;c2i<32;c2i++){
        int c=2*c2i;
        float ga=g_ctx[base+(size_t)c*Pn]*i0;
        float gb=g_ctx[base+(size_t)(c+1)*Pn]*i0;
        float ha=g_ctx[base+(size_t)(Cn+c)*Pn]*i1;
        float hb=g_ctx[base+(size_t)(Cn+c+1)*Pn]*i1;
        float ta=g_ctx[base+(size_t)(2*Cn+c)*Pn]*i2;
        float tb=g_ctx[base+(size_t)(2*Cn+c+1)*Pn]*i2;
        g_ctx[base+(size_t)c*Pn]=ga;
        g_ctx[base+(size_t)(c+1)*Pn]=gb;
        g_ctx[base+(size_t)(Cn+c)*Pn]=ha;
        g_ctx[base+(size_t)(Cn+c+1)*Pn]=hb;
        g_ctx[base+(size_t)(2*Cn+c)*Pn]=ta;
        g_ctx[base+(size_t)(2*Cn+c+1)*Pn]=tb;
        g_ctxh[hbase+(size_t)c2i*Pn]      =packh2(ga,gb);
        g_ctxh[hbase+(size_t)(32+c2i)*Pn] =packh2(ha,hb);
        g_ctxh[hbase+(size_t)(64+c2i)*Pn] =packh2(ta,tb);
        float ma=(ga+ha+ta)*(1.f/3.f);
        float mb=(gb+hb+tb)*(1.f/3.f);
        float d0=ga-ma,d1=ha-ma,d2=ta-ma,d3=gb-mb,d4=hb-mb,d5=tb-mb;
        ss+=d0*d0+d1*d1+d2*d2+d3*d3+d4*d4+d5*d5;
    }
    float cov=((c0>0.f?1.f:0.f)+(c1>0.f?1.f:0.f)+(c2>0.f?1.f:0.f))*(1.f/3.f);
    cov=fminf(cov,1.f);
    float uraw=sqrtf(ss*(1.f/(3.f*Cn)));
    g_ctx[base+(size_t)192*Pn]=cov;
    g_uraw[i]=uraw;
    float m=uraw;
    #pragma unroll
    for(int o=16;o>0;o>>=1) m=fmaxf(m,__shfl_xor_sync(0xffffffffu,m,o));
    if((threadIdx.x&31)==0) atomicMax(&g_umax[b], __float_as_int(m));
}

__global__ void k_uncert(float* __restrict__ dout){
    int i=blockIdx.x*blockDim.x+threadIdx.x;
    int b=i>>16, px=i&(Pn-1);
    size_t base=(size_t)b*C3n*Pn+px;
    float cov=g_ctx[base+(size_t)192*Pn];
    float sc=fmaxf(__int_as_float(g_umax[b]),1e-6f);
    float un=fminf(fmaxf(g_uraw[i]/sc,0.f),1.f)*cov;
    g_ctx[base+(size_t)193*Pn]=un;
    g_ctxh[((size_t)b*112+96)*Pn+px]=packh2(cov,un);
    dout[OFF_COV+i]=cov;
    dout[OFF_UNC+i]=un;
}

template<int MODE,int CIB>
__global__ void k_wtrans(const float* __restrict__ w){
    constexpr int CIN =(MODE==0)?C3n:COn;
    constexpr int NG  =3*CIB;
    int n=NG*192*BROW;
    int i=blockIdx.x*blockDim.x+threadIdx.x;
    if(i>=n) return;
    int grp=i/(192*BROW);
    int r=i-grp*(192*BROW);
    int co=r/BROW, k=r-co*BROW;
    float v=0.f;
    if(k<96){
        int dy=grp/CIB, cib=grp-dy*CIB;
        int dx=k>>5, ci=cib*32+(k&31);
        int tap=dy*3+dx;
        v=(ci<CIN)?w[((size_t)co*CIN+ci)*9+tap]:0.f;
    }
    unsigned short hv=__half_as_ushort(__float2half_rn(v));
    if(MODE==0) g_wTc1h[i]=hv; else g_wTc2h[i]=hv;
}

constexpr int SMA=9728;
constexpr int SMBb=19968;
constexpr int SMB0b=2*SMA;
constexpr int SM_BYTES=SMB0b+2*SMBb;

template<int CI2,int CI2P,int CIB,int MODE>
__global__ void __launch_bounds__(256,2) k_mconv(const float* __restrict__ bias){
    constexpr int NG=3*CIB;
    extern __shared__ __align__(1024) char smem[];
    const uint32_t* inH=(MODE==0)?g_ctxh:g_h1h;
    uint32_t* outR=(MODE==0)?g_h1r:g_h2r;
    const unsigned short* wT=(MODE==0)?g_wTc1h:g_wTc2h;
    const int tid=threadIdx.x, wid=tid>>5, lane=tid&31;
    const int sb=blockIdx.x, cn=blockIdx.y, b=blockIdx.z;
    const int y=sb>>1, x0=(sb&1)*128;
    const uint32_t* inB=inH+(size_t)b*CI2P*Pn;
    const uint32_t sbase=smem_u32(smem);
    const uint32_t* Aw=(const uint32_t*)smem;

    const int wm=wid&3, wn=wid>>2;
    const int g=lane>>2, tig=lane&3;
    const int nrow=(lane&7)+((lane>>4)<<3);
    const uint32_t blane=(uint32_t)(nrow*208+((lane&8)?16:0));

    float acc[2][6][4];
    #pragma unroll
    for(int mt=0;mt<2;mt++)
        #pragma unroll
        for(int nt=0;nt<6;nt++)
            #pragma unroll
            for(int q=0;q<4;q++) acc[mt][nt][q]=0.f;

    auto prefA=[&](int grp,int buf){
        int dy=grp/CIB, cib=grp-dy*CIB;
        int gy=y+dy-1;
        bool rok=((unsigned)gy<256u);
        uint32_t ab=sbase+(uint32_t)buf*SMA;
        #pragma unroll 1
        for(int l=tid;l<576;l+=256){
            int ci=l/36, v=l-ci*36;
            int ci2g=cib*16+ci;
            int px0=x0-8+4*v;
            bool ok=rok&&(ci2g<CI2)&&((unsigned)px0<253u);
            const uint32_t* src=inB+(size_t)(ok?ci2g:0)*Pn+(ok?(gy*256+px0):0);
            unsigned sz=ok?16u:0u;
            asm volatile("cp.async.cg.shared.global [%0],[%1],16,%2;"
                ::"r"(ab+(uint32_t)(ci*152+4*v)*4u),"l"(src),"r"(sz));
        }
    };
    auto prefB=[&](int grp,int buf){
        const float4* ws=(const float4*)(wT+(size_t)grp*(192*BROW)+(size_t)cn*(96*BROW));
        uint32_t bd=sbase+SMB0b+(uint32_t)buf*SMBb;
        #pragma unroll 1
        for(int l=tid;l<1248;l+=256)
            asm volatile("cp.async.cg.shared.global [%0],[%1],16;"
                ::"r"(bd+(uint32_t)l*16u),"l"(ws+l));
    };

    prefA(0,0); prefB(0,0);
    asm volatile("cp.async.commit_group;");

    #pragma unroll 1
    for(int grp=0;grp<NG;grp++){
        asm volatile("cp.async.wait_group 0;");
        __syncthreads();
        if(grp+1<NG){
            prefA(grp+1,(grp+1)&1);
            prefB(grp+1,(grp+1)&1);
            asm volatile("cp.async.commit_group;");
        }
        const int buf=grp&1;
        const uint32_t* As=Aw+buf*(SMA/4);
        const uint32_t bbase=sbase+SMB0b+(uint32_t)buf*SMBb+blane;
        #pragma unroll
        for(int kk=0;kk<6;kk++){
            const int dx=kk>>1;
            uint32_t bf[3][4];
            #pragma unroll
            for(int p=0;p<3;p++)
                ldmx4(bf[p], bbase+(uint32_t)((wn*48+p*16)*208)+(uint32_t)(kk*32));
            const int arow=((kk&1)*8+tig)*152;
            const int pxo=dx+7+g;
            #pragma unroll
            for(int mt=0;mt<2;mt++){
                uint32_t af[4];
                int ab=arow+wm*32+mt*16+pxo;
                af[0]=As[ab];
                af[1]=As[ab+8];
                af[2]=As[ab+4*152];
                af[3]=As[ab+4*152+8];
                #pragma unroll
                for(int nt=0;nt<6;nt++)
                    mma_f16(acc[mt][nt], af, &bf[nt>>1][(nt&1)*2]);
            }
        }
    }

    // epilogue: bias + packed fp16 stores + fused per-channel sum/sumsq
    const int row0=wm*32+(lane>>2);
    const int col0=cn*96+wn*48+2*(lane&3);
    const size_t pxb=(size_t)y*256+x0;
    float sa[6][2], qa[6][2];
    #pragma unroll
    for(int nt=0;nt<6;nt++){ sa[nt][0]=0;sa[nt][1]=0;qa[nt][0]=0;qa[nt][1]=0; }

    #pragma unroll
    for(int mt=0;mt<2;mt++){
        int r0=row0+mt*16;
        #pragma unroll
        for(int nt=0;nt<6;nt++){
            int co=col0+nt*8;
            float b0=__ldg(bias+co), b1=__ldg(bias+co+1);
            float v0=acc[mt][nt][0]+b0, v1=acc[mt][nt][1]+b1;
            float v2=acc[mt][nt][2]+b0, v3=acc[mt][nt][3]+b1;
            uint32_t* op=outR+((size_t)(b*96+(co>>1)))*Pn+pxb;
            op[r0]  =packh2(v0,v1);
            op[r0+8]=packh2(v2,v3);
            sa[nt][0]+=v0+v2; qa[nt][0]+=v0*v0+v2*v2;
            sa[nt][1]+=v1+v3; qa[nt][1]+=v1*v1+v3*v3;
        }
    }
    #pragma unroll
    for(int nt=0;nt<6;nt++)
        #pragma unroll
        for(int h=0;h<2;h++){
            float s=sa[nt][h], q=qa[nt][h];
            #pragma unroll
            for(int o=4;o<32;o<<=1){
                s+=__shfl_xor_sync(0xffffffffu,s,o);
                q+=__shfl_xor_sync(0xffffffffu,q,o);
            }
            if(lane<4){
                int co=col0+nt*8+h;
                atomicAdd(&g_csum[(b*COn+co)*2],s);
                atomicAdd(&g_csum[(b*COn+co)*2+1],q);
            }
        }
}

__global__ void k_stats(const float* __restrict__ scale, const float* __restrict__ shift){
    __shared__ float gm[16], gr[16];
    int t=threadIdx.x;
    if(t<Bn*8){
        int b=t/8, g=t%8;
        float s=0.f,q=0.f;
        for(int c=0;c<24;c++){
            s+=g_csum[(b*COn+g*24+c)*2];
            q+=g_csum[(b*COn+g*24+c)*2+1];
        }
        float N=24.f*(float)Pn;
        float mean=s/N;
        float var=q/N-mean*mean;
        gm[t]=mean;
        gr[t]=rsqrtf(var+1e-5f);
    }
    __syncthreads();
    if(t<Bn*COn){
        int b=t/COn, c=t%COn, g=c/24;
        float a=gr[b*8+g]*scale[c];
        g_sA[t]=a;
        g_sB[t]=shift[c]-gm[b*8+g]*a;
        g_csum[t*2]=0.f; g_csum[t*2+1]=0.f;
    }
}

__global__ void k_apply1(){
    int px=blockIdx.x*blockDim.x+threadIdx.x;
    int c2=blockIdx.y, b=blockIdx.z;
    int bc=b*COn+2*c2;
    uint32_t w=g_h1r[((size_t)(b*96+c2))*Pn+px];
    __half2 hh=*reinterpret_cast<__half2*>(&w);
    float v0=siluf(__low2float(hh)*g_sA[bc]+g_sB[bc]);
    float v1=siluf(__high2float(hh)*g_sA[bc+1]+g_sB[bc+1]);
    g_h1h[((size_t)b*96+c2)*Pn+px]=packh2(v0,v1);
}

// pooled mean of silu(GN2(h2)) per channel pair (fp16 h2)
__global__ void k_poolsum(){
    __shared__ float r0[256], r1[256];
    int bc2=blockIdx.x;
    int b=bc2/96, c2=bc2-b*96;
    int bc=b*COn+2*c2;
    const uint32_t* p=g_h2r+(size_t)bc2*Pn;
    float a0=g_sA[bc], s00=g_sB[bc];
    float a1=g_sA[bc+1], s01=g_sB[bc+1];
    float s0=0.f, s1=0.f;
    for(int i=threadIdx.x;i<Pn;i+=256){
        uint32_t w=p[i];
        __half2 hh=*reinterpret_cast<__half2*>(&w);
        s0+=siluf(__low2float(hh)*a0+s00);
        s1+=siluf(__high2float(hh)*a1+s01);
    }
    r0[threadIdx.x]=s0; r1[threadIdx.x]=s1;
    __syncthreads();
    for(int st=128;st>0;st>>=1){
        if(threadIdx.x<st){ r0[threadIdx.x]+=r0[threadIdx.x+st]; r1[threadIdx.x]+=r1[threadIdx.x+st]; }
        __syncthreads();
    }
    if(threadIdx.x==0){ g_pool[bc]=r0[0]; g_pool[bc+1]=r1[0]; }
}

__global__ void k_gate(const float* __restrict__ gw1, const float* __restrict__ gb1,
                       const float* __restrict__ gw2, const float* __restrict__ gb2){
    __shared__ float pooled[COn];
    __shared__ float hbuf[HIDn];
    for(int b=0;b<Bn;b++){
        for(int c=threadIdx.x;c<COn;c+=blockDim.x)
            pooled[c]=g_pool[b*COn+c]*(1.f/(float)Pn);
        __syncthreads();
        if(threadIdx.x<HIDn){
            float s=gb1[threadIdx.x];
            for(int c=0;c<COn;c++) s+=gw1[threadIdx.x*COn+c]*pooled[c];
            hbuf[threadIdx.x]=siluf(s);
        }
        __syncthreads();
        if(threadIdx.x<COn){
            float s=gb2[threadIdx.x];
            for(int j=0;j<HIDn;j++) s+=gw2[threadIdx.x*HIDn+j]*hbuf[j];
            g_gate[b*COn+threadIdx.x]=0.5f+sigf(s);
        }
        __syncthreads();
    }
}

__device__ __forceinline__ ull pack2(float v){ ull r; asm("mov.b64 %0,{%1,%1};":"=l"(r):"f"(v)); return r; }
__device__ __forceinline__ void fma2(ull&a, ull x, ull w){ asm("fma.rn.f32x2 %0,%1,%2,%0;":"+l"(a):"l"(x),"l"(w)); }
__device__ __forceinline__ void unpack2(ull v, float&lo, float&hi){ asm("mov.b64 {%0,%1},%2;":"=f"(lo),"=f"(hi):"l"(v)); }

__global__ void __launch_bounds__(256) k_res_combine(
    const float* __restrict__ rpw, const float* __restrict__ rpb,
    const float* __restrict__ prs, const float* __restrict__ pmix,
    const float* __restrict__ cfw, const float* __restrict__ cfb,
    float* __restrict__ dout){
    __shared__ __align__(16) float s_w[98*64];
    __shared__ float s_cwb[98];
    __shared__ float s_sA[64], s_sB[64], s_g[64];
    const int br=blockIdx.y, b=blockIdx.z;
    const int og=threadIdx.x>>6, pl=threadIdx.x&63;
    const int pxb=blockIdx.x*256;
    const float* ctxb=g_ctx+(size_t)b*C3n*Pn;
    const uint32_t* ctxhb=g_ctxh+(size_t)b*112*Pn;

    if(threadIdx.x<64){
        int bc=b*COn+br*64+threadIdx.x;
        s_sA[threadIdx.x]=g_sA[bc];
        s_sB[threadIdx.x]=g_sB[bc];
        s_g[threadIdx.x]=g_gate[bc];
    }

    ull acc[4][8];
    #pragma unroll
    for(int k=0;k<4;k++)
        #pragma unroll
        for(int j=0;j<8;j++) acc[k][j]=0;
    float cf[4]={0.f,0.f,0.f,0.f};

    #pragma unroll 1
    for(int half=0;half<2;half++){
        const int ci0=half?96:0;
        const int nci=half?98:96;
        const int p0=half?48:0;
        for(int l=threadIdx.x;l<nci*64;l+=256){
            int ci=l>>6, o=l&63;
            s_w[l]=rpw[(size_t)(br*64+o)*C3n+ci0+ci];
        }
        if(threadIdx.x<nci) s_cwb[threadIdx.x]=cfw[br*C3n+ci0+threadIdx.x];
        __syncthreads();
        #pragma unroll 1
        for(int p=0;p<(half?49:48);p++){
            const uint32_t* xp=ctxhb+(size_t)(p0+p)*Pn+pxb+pl;
            uint32_t w0=xp[0], w1=xp[64], w2=xp[128], w3=xp[192];
            __half2 h0=*reinterpret_cast<__half2*>(&w0);
            __half2 h1=*reinterpret_cast<__half2*>(&w1);
            __half2 h2=*reinterpret_cast<__half2*>(&w2);
            __half2 h3=*reinterpret_cast<__half2*>(&w3);
            float xa0=__low2float(h0), xb0=__high2float(h0);
            float xa1=__low2float(h1), xb1=__high2float(h1);
            float xa2=__low2float(h2), xb2=__high2float(h2);
            float xa3=__low2float(h3), xb3=__high2float(h3);
            float cwa=s_cwb[2*p], cwb=s_cwb[2*p+1];
            cf[0]+=xa0*cwa+xb0*cwb;
            cf[1]+=xa1*cwa+xb1*cwb;
            cf[2]+=xa2*cwa+xb2*cwb;
            cf[3]+=xa3*cwa+xb3*cwb;
            ull pa0=pack2(xa0), pa1=pack2(xa1), pa2=pack2(xa2), pa3=pack2(xa3);
            ull pb0=pack2(xb0), pb1=pack2(xb1), pb2=pack2(xb2), pb3=pack2(xb3);
            const ull* wra=reinterpret_cast<const ull*>(s_w+(2*p)*64+og*16);
            const ull* wrb=reinterpret_cast<const ull*>(s_w+(2*p+1)*64+og*16);
            #pragma unroll
            for(int j=0;j<8;j++){
                ull wa=wra[j];
                fma2(acc[0][j],pa0,wa); fma2(acc[1][j],pa1,wa);
                fma2(acc[2][j],pa2,wa); fma2(acc[3][j],pa3,wa);
            }
            #pragma unroll
            for(int j=0;j<8;j++){
                ull wb=wrb[j];
                fma2(acc[0][j],pb0,wb); fma2(acc[1][j],pb1,wb);
                fma2(acc[2][j],pb2,wb); fma2(acc[3][j],pb3,wb);
            }
        }
        __syncthreads();
    }

    const float trs=tanhf(prs[0]);
    const float ms=tanhf(pmix[0]);
    const float cb=cfb[br];
    const uint32_t* h2b=g_h2r+(size_t)b*96*Pn;
    #pragma unroll
    for(int k=0;k<4;k++){
        int px=pxb+pl+k*64;
        float confv=sigf(cf[k]+cb);
        dout[OFF_CONF+((size_t)(b*3+br))*Pn+px]=confv;
        #pragma unroll
        for(int j=0;j<8;j++){
            float lo,hi; unpack2(acc[k][j],lo,hi);
            int c0=og*16+2*j;
            int co=br*64+c0;
            uint32_t hw=h2b[(size_t)(co>>1)*Pn+px];
            __half2 hh=*reinterpret_cast<__half2*>(&hw);
            float hr0=__low2float(hh), hr1=__high2float(hh);
            float res0=lo+rpb[co],   res1=hi+rpb[co+1];
            float hv0=siluf(hr0*s_sA[c0]+s_sB[c0]);
            float hv1=siluf(hr1*s_sA[c0+1]+s_sB[c0+1]);
            float rf0=hv0*s_g[c0]+trs*res0;
            float rf1=hv1*s_g[c0+1]+trs*res1;
            float f0=ctxb[(size_t)co*Pn+px];
            float f1=ctxb[(size_t)(co+1)*Pn+px];
            dout[(size_t)br*((size_t)Bn*Cn*Pn)+((size_t)(b*Cn+c0))*Pn+px]  =f0+ms*rf0*confv;
            dout[(size_t)br*((size_t)Bn*Cn*Pn)+((size_t)(b*Cn+c0+1))*Pn+px]=f1+ms*rf1*confv;
        }
    }
}

extern "C" void kernel_launch(void* const* d_in, const int* in_sizes, int n_in,
                              void* d_out, int out_size){
    const float* vf   =(const float*)d_in[0];
    const float* uvs  =(const float*)d_in[1];
    const float* msk  =(const float*)d_in[2];
    const float* wg   =(const float*)d_in[3];
    const float* wb   =(const float*)d_in[4];
    const float* wh   =(const float*)d_in[5];
    const float* c1w  =(const float*)d_in[7];
    const float* c1b  =(const float*)d_in[8];
    const float* g1s  =(const float*)d_in[9];
    const float* g1b  =(const float*)d_in[10];
    const float* c2w  =(const float*)d_in[11];
    const float* c2b  =(const float*)d_in[12];
    const float* g2s  =(const float*)d_in[13];
    const float* g2b  =(const float*)d_in[14];
    const float* gw1  =(const float*)d_in[15];
    const float* gb1  =(const float*)d_in[16];
    const float* gw2  =(const float*)d_in[17];
    const float* gb2  =(const float*)d_in[18];
    const float* rpw  =(const float*)d_in[19];
    const float* rpb  =(const float*)d_in[20];
    const float* rs   =(const float*)d_in[21];
    const float* cfw  =(const float*)d_in[22];
    const float* cfb  =(const float*)d_in[23];
    const float* mixs =(const float*)d_in[24];
    float* dout=(float*)d_out;

    static int smem_set=0;
    if(!smem_set){
        cudaFuncSetAttribute(k_mconv<97,112,7,0>,
            cudaFuncAttributeMaxDynamicSharedMemorySize, SM_BYTES);
        cudaFuncSetAttribute(k_mconv<96,96,6,1>,
            cudaFuncAttributeMaxDynamicSharedMemorySize, SM_BYTES);
        smem_set=1;
    }

    k_zero<<<512,256>>>();                                          // 0
    k_scatter<<<dim3(64,16),256>>>(vf,uvs,msk,wg,wb,wh);            // 1
    k_finalize<<<512,256>>>();                                      // 2
    k_wtrans<0,7><<<(NG1*192*BROW+255)/256,256>>>(c1w);             // 3
    k_wtrans<1,6><<<(NG2*192*BROW+255)/256,256>>>(c2w);             // 4
    k_uncert<<<512,256>>>(dout);                                    // 5
    k_mconv<97,112,7,0><<<dim3(512,2,Bn),256,SM_BYTES>>>(c1b);      // 6
    k_stats<<<1,384>>>(g1s,g1b);                                    // 7
    k_apply1<<<dim3(256,96,2),256>>>();                             // 8
    k_mconv<96,96,6,1><<<dim3(512,2,Bn),256,SM_BYTES>>>(c2b);       // 9
    k_stats<<<1,384>>>(g2s,g2b);                                    // 10
    k_poolsum<<<Bn*96,256>>>();                                     // 11
    k_gate<<<1,192>>>(gw1,gb1,gw2,gb2);                             // 12
    k_res_combine<<<dim3(256,3,2),256>>>(rpw,rpb,rs,mixs,cfw,cfb,dout); // 13
}